// round 2
// baseline (speedup 1.0000x reference)
#include <cuda_runtime.h>
#include <cstdint>

#define K_FEAT 256
#define TM 128          // pixel tile
#define TN 128          // symbol tile
#define KC 16           // K chunk
#define STR 132         // padded row stride (floats) for transposed smem tiles

__device__ double g_devsum;
__device__ float  g_wnorm[8192];   // full ||w_s||^2

// ---------------- packed f32x2 helpers (sm_100+) ----------------
__device__ __forceinline__ unsigned long long pack2(float lo, float hi) {
    unsigned long long r;
    asm("mov.b64 %0, {%1, %2};" : "=l"(r) : "f"(lo), "f"(hi));
    return r;
}
__device__ __forceinline__ void unpack2(unsigned long long v, float& lo, float& hi) {
    asm("mov.b64 {%0, %1}, %2;" : "=f"(lo), "=f"(hi) : "l"(v));
}
__device__ __forceinline__ void ffma2(unsigned long long& d, unsigned long long a,
                                      unsigned long long b) {
    asm("fma.rn.f32x2 %0, %1, %2, %0;" : "+l"(d) : "l"(a), "l"(b));
}

// ---------------- kernel 1: ||W_s||^2 (full) + zero the deviation accumulator --------
__global__ void wnorm_kernel(const float* __restrict__ W, int S) {
    int s = blockIdx.x;
    __shared__ float red[8];
    float v = W[(long long)s * K_FEAT + threadIdx.x];
    float acc = v * v;
    #pragma unroll
    for (int o = 16; o; o >>= 1) acc += __shfl_xor_sync(0xffffffffu, acc, o);
    if ((threadIdx.x & 31) == 0) red[threadIdx.x >> 5] = acc;
    __syncthreads();
    if (threadIdx.x == 0) {
        float t = 0.f;
        #pragma unroll
        for (int i = 0; i < 8; i++) t += red[i];
        g_wnorm[s] = t;                      // FULL ||w||^2 (reference form)
        if (s == 0) g_devsum = 0.0;
    }
}

// ---------------- kernel 2: distances GEMM + argmin + gather + deviation -------------
extern __shared__ float smem_f[];

__global__ void __launch_bounds__(256, 1)
vq_kernel(const float* __restrict__ X, const float* __restrict__ W,
          float* __restrict__ out, int npix, int S, long long out_cap)
{
    // smem layout (floats)
    float* xs      = smem_f;                    // [K_FEAT][STR]  x tile transposed [k][row]
    float* ws      = xs + K_FEAT * STR;         // [2][KC][STR]   W chunk double buffer
    float* Arow    = ws + 2 * KC * STR;         // [TM]           ||x||^2 per row
    float* scratch = Arow + TM;                 // 8320 floats, multi-use
    // phase 1 use: part[128][65] quad-sums for Arow
    // phase 2 use: red_s[128*17], red_i[128*17], code[128], psum[256]
    float* part  = scratch;
    float* red_s = scratch;
    int*   red_i = (int*)(red_s + TM * 17);
    int*   code  = red_i + TM * 17;
    float* psum  = (float*)(code + TM);

    const int tid = threadIdx.x;
    const int tx = tid & 15, ty = tid >> 4;
    const int p0 = blockIdx.x * TM;

    const float4* Xg4 = (const float4*)X;
    const float4* Wg4 = (const float4*)W;

    // ---- load x tile transposed + per-quad x^2 partials ----
    #pragma unroll 4
    for (int i = 0; i < 32; i++) {
        int q = i * 256 + tid;     // 0..8191
        int row = q >> 6;          // = 4*i + (tid>>6)
        int kq  = q & 63;          // = tid & 63
        float4 v = make_float4(0.f, 0.f, 0.f, 0.f);
        if (p0 + row < npix) v = Xg4[(long long)(p0 + row) * 64 + kq];
        xs[(kq * 4 + 0) * STR + row] = v.x;
        xs[(kq * 4 + 1) * STR + row] = v.y;
        xs[(kq * 4 + 2) * STR + row] = v.z;
        xs[(kq * 4 + 3) * STR + row] = v.w;
        part[row * 65 + kq] = ((v.x * v.x + v.y * v.y) + v.z * v.z) + v.w * v.w;
    }
    __syncthreads();

    // deterministic per-row sum of 64 quad partials -> Arow
    if (tid < TM) {
        float a = 0.f;
        #pragma unroll
        for (int kq = 0; kq < 64; kq++) a += part[tid * 65 + kq];
        Arow[tid] = a;
    }
    __syncthreads();

    float a_r[8];
    #pragma unroll
    for (int i = 0; i < 8; i++) a_r[i] = Arow[ty * 8 + i];

    float dbest[8];
    int   didx[8];
    #pragma unroll
    for (int i = 0; i < 8; i++) { dbest[i] = 3.4e38f; didx[i] = 0; }

    const int ntile = S / TN;
    for (int st = 0; st < ntile; st++) {
        const int sbase = st * TN;

        // load chunk 0 into buffer 0
        {
            float4 v[2];
            #pragma unroll
            for (int j = 0; j < 2; j++) {
                int idx = j * 256 + tid;
                int srow = idx >> 2, kq4 = idx & 3;
                v[j] = Wg4[(long long)(sbase + srow) * 64 + kq4];
            }
            #pragma unroll
            for (int j = 0; j < 2; j++) {
                int idx = j * 256 + tid;
                int srow = idx >> 2, kq4 = idx & 3;
                ws[(kq4 * 4 + 0) * STR + srow] = v[j].x;
                ws[(kq4 * 4 + 1) * STR + srow] = v[j].y;
                ws[(kq4 * 4 + 2) * STR + srow] = v[j].z;
                ws[(kq4 * 4 + 3) * STR + srow] = v[j].w;
            }
        }
        __syncthreads();

        unsigned long long acc[4][8];
        #pragma unroll
        for (int i = 0; i < 4; i++)
            #pragma unroll
            for (int j = 0; j < 8; j++) acc[i][j] = 0ull;

        #pragma unroll 1
        for (int kc = 0; kc < K_FEAT / KC; kc++) {
            float4 pf[2];
            const bool more = (kc + 1 < K_FEAT / KC);
            if (more) {
                #pragma unroll
                for (int j = 0; j < 2; j++) {
                    int idx = j * 256 + tid;
                    int srow = idx >> 2, kq4 = idx & 3;
                    pf[j] = Wg4[(long long)(sbase + srow) * 64 + (kc + 1) * 4 + kq4];
                }
            }
            const float* wb = ws + (kc & 1) * KC * STR;
            const float* xb = xs + kc * KC * STR;
            #pragma unroll
            for (int k = 0; k < KC; k++) {
                ulonglong2 a01 = *(const ulonglong2*)(xb + k * STR + ty * 8);
                ulonglong2 a23 = *(const ulonglong2*)(xb + k * STR + ty * 8 + 4);
                float4 b0 = *(const float4*)(wb + k * STR + tx * 8);
                float4 b1 = *(const float4*)(wb + k * STR + tx * 8 + 4);
                unsigned long long aa[4] = {a01.x, a01.y, a23.x, a23.y};
                unsigned long long bb[8];
                bb[0] = pack2(b0.x, b0.x); bb[1] = pack2(b0.y, b0.y);
                bb[2] = pack2(b0.z, b0.z); bb[3] = pack2(b0.w, b0.w);
                bb[4] = pack2(b1.x, b1.x); bb[5] = pack2(b1.y, b1.y);
                bb[6] = pack2(b1.z, b1.z); bb[7] = pack2(b1.w, b1.w);
                #pragma unroll
                for (int i = 0; i < 4; i++)
                    #pragma unroll
                    for (int j = 0; j < 8; j++)
                        ffma2(acc[i][j], aa[i], bb[j]);
            }
            if (more) {
                __syncthreads();
                float* wn = ws + ((kc + 1) & 1) * KC * STR;
                #pragma unroll
                for (int j = 0; j < 2; j++) {
                    int idx = j * 256 + tid;
                    int srow = idx >> 2, kq4 = idx & 3;
                    wn[(kq4 * 4 + 0) * STR + srow] = pf[j].x;
                    wn[(kq4 * 4 + 1) * STR + srow] = pf[j].y;
                    wn[(kq4 * 4 + 2) * STR + srow] = pf[j].z;
                    wn[(kq4 * 4 + 3) * STR + srow] = pf[j].w;
                }
                __syncthreads();
            }
        }

        // epilogue: d = fl(fl(A + B) - 2*dot), running argmin (ties -> lowest index).
        // Within a thread we scan symbol indices in ascending order, so a strict '<'
        // keeps the first (lowest-index) minimum automatically.
        float wnj[8];
        #pragma unroll
        for (int j = 0; j < 8; j++) wnj[j] = g_wnorm[sbase + tx * 8 + j];
        #pragma unroll
        for (int i = 0; i < 4; i++) {
            #pragma unroll
            for (int j = 0; j < 8; j++) {
                float lo, hi;
                unpack2(acc[i][j], lo, hi);
                const int sidx = sbase + tx * 8 + j;
                const float t0 = __fadd_rn(a_r[2 * i], wnj[j]);
                const float d0 = __fmaf_rn(-2.0f, lo, t0);
                const float t1 = __fadd_rn(a_r[2 * i + 1], wnj[j]);
                const float d1 = __fmaf_rn(-2.0f, hi, t1);
                if (d0 < dbest[2 * i])     { dbest[2 * i] = d0;     didx[2 * i] = sidx; }
                if (d1 < dbest[2 * i + 1]) { dbest[2 * i + 1] = d1; didx[2 * i + 1] = sidx; }
            }
        }
        __syncthreads();
    }

    // ---- cross-thread (tx) argmin reduction per pixel row ----
    #pragma unroll
    for (int i = 0; i < 8; i++) {
        int row = ty * 8 + i;
        red_s[row * 17 + tx] = dbest[i];
        red_i[row * 17 + tx] = didx[i];
    }
    __syncthreads();
    if (tid < TM) {
        float bs = red_s[tid * 17 + 0];
        int   bi = red_i[tid * 17 + 0];
        #pragma unroll
        for (int t = 1; t < 16; t++) {
            float s  = red_s[tid * 17 + t];
            int   ix = red_i[tid * 17 + t];
            if (s < bs || (s == bs && ix < bi)) { bs = s; bi = ix; }
        }
        code[tid] = bi;
    }
    __syncthreads();

    // ---- gather W[code], write out = x + (w - x) (exact ref rounding), deviation ----
    float4* out4 = (float4*)out;
    float dsum = 0.f;
    #pragma unroll 4
    for (int i = 0; i < 32; i++) {
        int q = i * 256 + tid;
        int row = q >> 6, kq = q & 63;
        long long gp = p0 + row;
        if (gp < npix) {
            int c = code[row];
            float4 wv = Wg4[(long long)c * 64 + kq];
            float4 xv = Xg4[gp * 64 + kq];
            float t0 = wv.x - xv.x, t1 = wv.y - xv.y;
            float t2 = wv.z - xv.z, t3 = wv.w - xv.w;
            float4 ov;
            ov.x = xv.x + t0; ov.y = xv.y + t1;
            ov.z = xv.z + t2; ov.w = xv.w + t3;
            long long e = gp * 64 + kq;
            if (e * 4 + 3 < out_cap) out4[e] = ov;
            dsum += t0 * t0 + t1 * t1 + t2 * t2 + t3 * t3;
        }
    }
    psum[tid] = dsum;
    __syncthreads();
    #pragma unroll
    for (int sft = 128; sft > 0; sft >>= 1) {
        if (tid < sft) psum[tid] += psum[tid + sft];
        __syncthreads();
    }
    if (tid == 0) atomicAdd(&g_devsum, (double)psum[0]);
}

// ---------------- kernel 3: write deviation scalar(s) at the output tail -------------
__global__ void final_kernel(float* out, long long n, long long out_size) {
    double dev = 1.25 * g_devsum / (double)n;
    for (long long i = n + threadIdx.x; i < out_size; i += blockDim.x)
        out[i] = (float)dev;
}

// ---------------- launch --------------------------------------------------------------
extern "C" void kernel_launch(void* const* d_in, const int* in_sizes, int n_in,
                              void* d_out, int out_size) {
    const float* X = (const float*)d_in[0];
    const float* W = (const float*)d_in[1];
    float* out = (float*)d_out;

    const int npix = in_sizes[0] / K_FEAT;     // 65536
    const int S    = in_sizes[1] / K_FEAT;     // 1024

    const size_t smem =
        (size_t)(K_FEAT * STR + 2 * KC * STR + TM + 8320) * sizeof(float);
    cudaFuncSetAttribute(vq_kernel, cudaFuncAttributeMaxDynamicSharedMemorySize, (int)smem);

    wnorm_kernel<<<S, 256>>>(W, S);
    const int grid = (npix + TM - 1) / TM;
    vq_kernel<<<grid, 256, smem>>>(X, W, out, npix, S, (long long)out_size);
    final_kernel<<<1, 256>>>(out, (long long)npix * (long long)K_FEAT, (long long)out_size);
}

// round 3
// speedup vs baseline: 1.0016x; 1.0016x over previous
#include <cuda_runtime.h>
#include <cstdint>

#define K_FEAT 256
#define TM 128          // pixel tile
#define TN 128          // symbol tile
#define KC 16           // K chunk
#define STR 132         // padded row stride (floats) for transposed smem tiles

__device__ double g_devsum;
__device__ float  g_wnorm[8192];   // full ||w_s||^2

// ---------------- packed f32x2 helpers (sm_100+) ----------------
__device__ __forceinline__ unsigned long long pack2(float lo, float hi) {
    unsigned long long r;
    asm("mov.b64 %0, {%1, %2};" : "=l"(r) : "f"(lo), "f"(hi));
    return r;
}
__device__ __forceinline__ void unpack2(unsigned long long v, float& lo, float& hi) {
    asm("mov.b64 {%0, %1}, %2;" : "=f"(lo), "=f"(hi) : "l"(v));
}
__device__ __forceinline__ void ffma2(unsigned long long& d, unsigned long long a,
                                      unsigned long long b) {
    asm("fma.rn.f32x2 %0, %1, %2, %0;" : "+l"(d) : "l"(a), "l"(b));
}

// ---------------- kernel 1: ||W_s||^2 (full) + zero the deviation accumulator --------
__global__ void wnorm_kernel(const float* __restrict__ W, int S) {
    int s = blockIdx.x;
    __shared__ float red[8];
    float v = W[(long long)s * K_FEAT + threadIdx.x];
    float acc = v * v;
    #pragma unroll
    for (int o = 16; o; o >>= 1) acc += __shfl_xor_sync(0xffffffffu, acc, o);
    if ((threadIdx.x & 31) == 0) red[threadIdx.x >> 5] = acc;
    __syncthreads();
    if (threadIdx.x == 0) {
        float t = 0.f;
        #pragma unroll
        for (int i = 0; i < 8; i++) t += red[i];
        g_wnorm[s] = t;                      // FULL ||w||^2 (reference form)
        if (s == 0) g_devsum = 0.0;
    }
}

// ---------------- kernel 2: distances GEMM + argmin + gather + deviation -------------
extern __shared__ float smem_f[];

__global__ void __launch_bounds__(256, 1)
vq_kernel(const float* __restrict__ X, const float* __restrict__ W,
          float* __restrict__ out, int npix, int S, long long out_cap)
{
    // smem layout (floats)
    float* xs      = smem_f;                    // [K_FEAT][STR]  x tile transposed [k][row]
    float* ws      = xs + K_FEAT * STR;         // [2][KC][STR]   W chunk double buffer
    float* Arow    = ws + 2 * KC * STR;         // [TM]           ||x||^2 per row
    float* scratch = Arow + TM;                 // 8320 floats, multi-use
    // phase 1 use: part[128][65] quad-sums for Arow
    // phase 2 use: red_s[128*17], red_i[128*17], code[128], psum[256]
    float* part  = scratch;
    float* red_s = scratch;
    int*   red_i = (int*)(red_s + TM * 17);
    int*   code  = red_i + TM * 17;
    float* psum  = (float*)(code + TM);

    const int tid = threadIdx.x;
    const int tx = tid & 15, ty = tid >> 4;
    const int p0 = blockIdx.x * TM;

    const float4* Xg4 = (const float4*)X;
    const float4* Wg4 = (const float4*)W;

    // ---- load x tile transposed + per-quad x^2 partials ----
    #pragma unroll 4
    for (int i = 0; i < 32; i++) {
        int q = i * 256 + tid;     // 0..8191
        int row = q >> 6;          // = 4*i + (tid>>6)
        int kq  = q & 63;          // = tid & 63
        float4 v = make_float4(0.f, 0.f, 0.f, 0.f);
        if (p0 + row < npix) v = Xg4[(long long)(p0 + row) * 64 + kq];
        xs[(kq * 4 + 0) * STR + row] = v.x;
        xs[(kq * 4 + 1) * STR + row] = v.y;
        xs[(kq * 4 + 2) * STR + row] = v.z;
        xs[(kq * 4 + 3) * STR + row] = v.w;
        part[row * 65 + kq] = ((v.x * v.x + v.y * v.y) + v.z * v.z) + v.w * v.w;
    }
    __syncthreads();

    // deterministic per-row sum of 64 quad partials -> Arow
    if (tid < TM) {
        float a = 0.f;
        #pragma unroll
        for (int kq = 0; kq < 64; kq++) a += part[tid * 65 + kq];
        Arow[tid] = a;
    }
    __syncthreads();

    float a_r[8];
    #pragma unroll
    for (int i = 0; i < 8; i++) a_r[i] = Arow[ty * 8 + i];

    float dbest[8];
    int   didx[8];
    #pragma unroll
    for (int i = 0; i < 8; i++) { dbest[i] = 3.4e38f; didx[i] = 0; }

    const int ntile = S / TN;
    for (int st = 0; st < ntile; st++) {
        const int sbase = st * TN;

        // load chunk 0 into buffer 0
        {
            float4 v[2];
            #pragma unroll
            for (int j = 0; j < 2; j++) {
                int idx = j * 256 + tid;
                int srow = idx >> 2, kq4 = idx & 3;
                v[j] = Wg4[(long long)(sbase + srow) * 64 + kq4];
            }
            #pragma unroll
            for (int j = 0; j < 2; j++) {
                int idx = j * 256 + tid;
                int srow = idx >> 2, kq4 = idx & 3;
                ws[(kq4 * 4 + 0) * STR + srow] = v[j].x;
                ws[(kq4 * 4 + 1) * STR + srow] = v[j].y;
                ws[(kq4 * 4 + 2) * STR + srow] = v[j].z;
                ws[(kq4 * 4 + 3) * STR + srow] = v[j].w;
            }
        }
        __syncthreads();

        unsigned long long acc[4][8];
        #pragma unroll
        for (int i = 0; i < 4; i++)
            #pragma unroll
            for (int j = 0; j < 8; j++) acc[i][j] = 0ull;

        #pragma unroll 1
        for (int kc = 0; kc < K_FEAT / KC; kc++) {
            float4 pf[2];
            const bool more = (kc + 1 < K_FEAT / KC);
            if (more) {
                #pragma unroll
                for (int j = 0; j < 2; j++) {
                    int idx = j * 256 + tid;
                    int srow = idx >> 2, kq4 = idx & 3;
                    pf[j] = Wg4[(long long)(sbase + srow) * 64 + (kc + 1) * 4 + kq4];
                }
            }
            const float* wb = ws + (kc & 1) * KC * STR;
            const float* xb = xs + kc * KC * STR;
            #pragma unroll
            for (int k = 0; k < KC; k++) {
                ulonglong2 a01 = *(const ulonglong2*)(xb + k * STR + ty * 8);
                ulonglong2 a23 = *(const ulonglong2*)(xb + k * STR + ty * 8 + 4);
                float4 b0 = *(const float4*)(wb + k * STR + tx * 8);
                float4 b1 = *(const float4*)(wb + k * STR + tx * 8 + 4);
                unsigned long long aa[4] = {a01.x, a01.y, a23.x, a23.y};
                unsigned long long bb[8];
                bb[0] = pack2(b0.x, b0.x); bb[1] = pack2(b0.y, b0.y);
                bb[2] = pack2(b0.z, b0.z); bb[3] = pack2(b0.w, b0.w);
                bb[4] = pack2(b1.x, b1.x); bb[5] = pack2(b1.y, b1.y);
                bb[6] = pack2(b1.z, b1.z); bb[7] = pack2(b1.w, b1.w);
                #pragma unroll
                for (int i = 0; i < 4; i++)
                    #pragma unroll
                    for (int j = 0; j < 8; j++)
                        ffma2(acc[i][j], aa[i], bb[j]);
            }
            if (more) {
                __syncthreads();
                float* wn = ws + ((kc + 1) & 1) * KC * STR;
                #pragma unroll
                for (int j = 0; j < 2; j++) {
                    int idx = j * 256 + tid;
                    int srow = idx >> 2, kq4 = idx & 3;
                    wn[(kq4 * 4 + 0) * STR + srow] = pf[j].x;
                    wn[(kq4 * 4 + 1) * STR + srow] = pf[j].y;
                    wn[(kq4 * 4 + 2) * STR + srow] = pf[j].z;
                    wn[(kq4 * 4 + 3) * STR + srow] = pf[j].w;
                }
                __syncthreads();
            }
        }

        // epilogue: d = fl(fl(A + B) - 2*dot), running argmin (ties -> lowest index).
        // Within a thread we scan symbol indices in ascending order, so a strict '<'
        // keeps the first (lowest-index) minimum automatically.
        float wnj[8];
        #pragma unroll
        for (int j = 0; j < 8; j++) wnj[j] = g_wnorm[sbase + tx * 8 + j];
        #pragma unroll
        for (int i = 0; i < 4; i++) {
            #pragma unroll
            for (int j = 0; j < 8; j++) {
                float lo, hi;
                unpack2(acc[i][j], lo, hi);
                const int sidx = sbase + tx * 8 + j;
                const float t0 = __fadd_rn(a_r[2 * i], wnj[j]);
                const float d0 = __fmaf_rn(-2.0f, lo, t0);
                const float t1 = __fadd_rn(a_r[2 * i + 1], wnj[j]);
                const float d1 = __fmaf_rn(-2.0f, hi, t1);
                if (d0 < dbest[2 * i])     { dbest[2 * i] = d0;     didx[2 * i] = sidx; }
                if (d1 < dbest[2 * i + 1]) { dbest[2 * i + 1] = d1; didx[2 * i + 1] = sidx; }
            }
        }
        __syncthreads();
    }

    // ---- cross-thread (tx) argmin reduction per pixel row ----
    #pragma unroll
    for (int i = 0; i < 8; i++) {
        int row = ty * 8 + i;
        red_s[row * 17 + tx] = dbest[i];
        red_i[row * 17 + tx] = didx[i];
    }
    __syncthreads();
    if (tid < TM) {
        float bs = red_s[tid * 17 + 0];
        int   bi = red_i[tid * 17 + 0];
        #pragma unroll
        for (int t = 1; t < 16; t++) {
            float s  = red_s[tid * 17 + t];
            int   ix = red_i[tid * 17 + t];
            if (s < bs || (s == bs && ix < bi)) { bs = s; bi = ix; }
        }
        code[tid] = bi;
    }
    __syncthreads();

    // ---- gather W[code], write out = x + (w - x) (exact ref rounding), deviation ----
    float4* out4 = (float4*)out;
    float dsum = 0.f;
    #pragma unroll 4
    for (int i = 0; i < 32; i++) {
        int q = i * 256 + tid;
        int row = q >> 6, kq = q & 63;
        long long gp = p0 + row;
        if (gp < npix) {
            int c = code[row];
            float4 wv = Wg4[(long long)c * 64 + kq];
            float4 xv = Xg4[gp * 64 + kq];
            float t0 = wv.x - xv.x, t1 = wv.y - xv.y;
            float t2 = wv.z - xv.z, t3 = wv.w - xv.w;
            float4 ov;
            ov.x = xv.x + t0; ov.y = xv.y + t1;
            ov.z = xv.z + t2; ov.w = xv.w + t3;
            long long e = gp * 64 + kq;
            if (e * 4 + 3 < out_cap) out4[e] = ov;
            dsum += t0 * t0 + t1 * t1 + t2 * t2 + t3 * t3;
        }
    }
    psum[tid] = dsum;
    __syncthreads();
    #pragma unroll
    for (int sft = 128; sft > 0; sft >>= 1) {
        if (tid < sft) psum[tid] += psum[tid + sft];
        __syncthreads();
    }
    if (tid == 0) atomicAdd(&g_devsum, (double)psum[0]);
}

// ---------------- kernel 3: write deviation scalar(s) at the output tail -------------
__global__ void final_kernel(float* out, long long n, long long out_size) {
    double dev = 1.25 * g_devsum / (double)n;
    for (long long i = n + threadIdx.x; i < out_size; i += blockDim.x)
        out[i] = (float)dev;
}

// ---------------- launch --------------------------------------------------------------
extern "C" void kernel_launch(void* const* d_in, const int* in_sizes, int n_in,
                              void* d_out, int out_size) {
    const float* X = (const float*)d_in[0];
    const float* W = (const float*)d_in[1];
    float* out = (float*)d_out;

    const int npix = in_sizes[0] / K_FEAT;     // 65536
    const int S    = in_sizes[1] / K_FEAT;     // 1024

    const size_t smem =
        (size_t)(K_FEAT * STR + 2 * KC * STR + TM + 8320) * sizeof(float);
    cudaFuncSetAttribute(vq_kernel, cudaFuncAttributeMaxDynamicSharedMemorySize, (int)smem);

    wnorm_kernel<<<S, 256>>>(W, S);
    const int grid = (npix + TM - 1) / TM;
    vq_kernel<<<grid, 256, smem>>>(X, W, out, npix, S, (long long)out_size);
    final_kernel<<<1, 256>>>(out, (long long)npix * (long long)K_FEAT, (long long)out_size);
}

// round 5
// speedup vs baseline: 1.1980x; 1.1960x over previous
#include <cuda_runtime.h>
#include <cuda_bf16.h>
#include <cstdint>

typedef unsigned long long u64;
typedef uint32_t u32;

#define MARGIN 2.5e-4f

__device__ double g_devsum;
__device__ int    g_flagcnt;
__device__ float  g_wnorm[1024];
__device__ int    g_code[65536];
__device__ int    g_flaglist[65536];
// [tile8][plane2][chunk4][sym128][k64] bf16  (16KB per chunk-region)
__device__ __align__(16) unsigned char g_wblob[8 * 2 * 4 * 16384];

__device__ __forceinline__ u32 smem_to_u32(const void* p) {
    u32 a;
    asm("{ .reg .u64 t; cvta.to.shared.u64 t, %1; cvt.u32.u64 %0, t; }" : "=r"(a) : "l"(p));
    return a;
}

#define LDSM4(r0, r1, r2, r3, addr) \
    asm volatile("ldmatrix.sync.aligned.m8n8.x4.shared.b16 {%0,%1,%2,%3}, [%4];" \
                 : "=r"(r0), "=r"(r1), "=r"(r2), "=r"(r3) : "r"(addr))

#define MMA16816(c0, c1, c2, c3, a0, a1, a2, a3, b0, b1) \
    asm volatile("mma.sync.aligned.m16n8k16.row.col.f32.bf16.bf16.f32 " \
                 "{%0,%1,%2,%3},{%4,%5,%6,%7},{%8,%9},{%0,%1,%2,%3};" \
                 : "+f"(c0), "+f"(c1), "+f"(c2), "+f"(c3) \
                 : "r"(a0), "r"(a1), "r"(a2), "r"(a3), "r"(b0), "r"(b1))

// ================= prep: wnorm (bitwise round-2) + W bf16 hi/lo blob ================
__global__ void prep_kernel(const float* __restrict__ W) {
    int s = blockIdx.x, tid = threadIdx.x;
    __shared__ float red[8];
    float v = W[s * 256 + tid];
    float acc = v * v;
    #pragma unroll
    for (int o = 16; o; o >>= 1) acc += __shfl_xor_sync(0xffffffffu, acc, o);
    if ((tid & 31) == 0) red[tid >> 5] = acc;
    __syncthreads();
    if (tid == 0) {
        float t = 0.f;
        #pragma unroll
        for (int i = 0; i < 8; i++) t += red[i];
        g_wnorm[s] = t;
        if (s == 0) { g_devsum = 0.0; g_flagcnt = 0; }
    }
    int tile = s >> 7, sym = s & 127, c = tid >> 6, k = tid & 63;
    __nv_bfloat16 hi = __float2bfloat16(v);
    __nv_bfloat16 lo = __float2bfloat16(v - __bfloat162float(hi));
    size_t off = (size_t)sym * 128 + k * 2;
    *(__nv_bfloat16*)(g_wblob + (size_t)((tile * 2 + 0) * 4 + c) * 16384 + off) = hi;
    *(__nv_bfloat16*)(g_wblob + (size_t)((tile * 2 + 1) * 4 + c) * 16384 + off) = lo;
}

// ================= vq: HMMA GEMM + margin argmin ====================================
#define SM_AHI   0          // 128 x 264 bf16 (stride 528B) = 67584
#define SM_ALO   67584
#define SM_BBUF  135168     // 2 x 18432 (128 x 72 bf16, stride 144B)
#define SM_PART  135168     // phase-0 overlay: 128 x 65 floats
#define SM_RED   135168     // final overlay: 128 x 16 x 2 u64 = 32768
#define SM_AROW  172032     // 128 floats
#define SM_TOTAL 172544

extern __shared__ char smem[];

__device__ __forceinline__ const uint4* region_ptr(int g) {
    int tile = g / 12, s = g - tile * 12;
    int pass = s >> 2, c = s & 3;
    int bp = (pass == 2) ? 1 : 0;
    return (const uint4*)(g_wblob + (size_t)((tile * 2 + bp) * 4 + c) * 16384);
}

__global__ void __launch_bounds__(256, 1)
vq_kernel(const float* __restrict__ X, int npix)
{
    const int tid = threadIdx.x, lane = tid & 31, wid = tid >> 5;
    const int warp_m = wid & 1, warp_n = wid >> 1;
    const int p0 = blockIdx.x * 128;
    const u32 sb = smem_to_u32(smem);

    // ---- phase 0: X -> A hi/lo smem + quad partials ----
    float* part = (float*)(smem + SM_PART);
    const float4* Xg4 = (const float4*)X;
    #pragma unroll 4
    for (int i = 0; i < 32; i++) {
        int q = i * 256 + tid, row = q >> 6, kq = q & 63;
        float4 v = make_float4(0.f, 0.f, 0.f, 0.f);
        if (p0 + row < npix) v = Xg4[(size_t)(p0 + row) * 64 + kq];
        __nv_bfloat16 h0 = __float2bfloat16(v.x), h1 = __float2bfloat16(v.y);
        __nv_bfloat16 h2 = __float2bfloat16(v.z), h3 = __float2bfloat16(v.w);
        u32 hx = (u32)__bfloat16_as_ushort(h0) | ((u32)__bfloat16_as_ushort(h1) << 16);
        u32 hy = (u32)__bfloat16_as_ushort(h2) | ((u32)__bfloat16_as_ushort(h3) << 16);
        *(uint2*)(smem + SM_AHI + row * 528 + kq * 8) = make_uint2(hx, hy);
        __nv_bfloat16 l0 = __float2bfloat16(v.x - __bfloat162float(h0));
        __nv_bfloat16 l1 = __float2bfloat16(v.y - __bfloat162float(h1));
        __nv_bfloat16 l2 = __float2bfloat16(v.z - __bfloat162float(h2));
        __nv_bfloat16 l3 = __float2bfloat16(v.w - __bfloat162float(h3));
        u32 lx = (u32)__bfloat16_as_ushort(l0) | ((u32)__bfloat16_as_ushort(l1) << 16);
        u32 ly = (u32)__bfloat16_as_ushort(l2) | ((u32)__bfloat16_as_ushort(l3) << 16);
        *(uint2*)(smem + SM_ALO + row * 528 + kq * 8) = make_uint2(lx, ly);
        part[row * 65 + kq] = ((v.x * v.x + v.y * v.y) + v.z * v.z) + v.w * v.w;
    }
    __syncthreads();
    float* arow = (float*)(smem + SM_AROW);
    if (tid < 128) {
        float a = 0.f;
        #pragma unroll
        for (int kq = 0; kq < 64; kq++) a += part[tid * 65 + kq];
        arow[tid] = a;
    }
    __syncthreads();
    float a_r[4][2];
    #pragma unroll
    for (int g = 0; g < 4; g++)
        #pragma unroll
        for (int h = 0; h < 2; h++)
            a_r[g][h] = arow[warp_m * 64 + g * 16 + (lane >> 2) + h * 8];
    __syncthreads();

    // ---- fill B chunk 0 ----
    {
        const uint4* src = region_ptr(0);
        #pragma unroll
        for (int j = 0; j < 4; j++) {
            int idx = j * 256 + tid, sym = idx >> 3, seg = idx & 7;
            *(uint4*)(smem + SM_BBUF + sym * 144 + seg * 16) = src[idx];
        }
    }
    __syncthreads();

    float acc[4][4][4];
    #pragma unroll
    for (int g = 0; g < 4; g++)
        #pragma unroll
        for (int n = 0; n < 4; n++)
            #pragma unroll
            for (int j = 0; j < 4; j++) acc[g][n][j] = 0.f;
    u64 m1[4][2], m2[4][2];
    #pragma unroll
    for (int g = 0; g < 4; g++) { m1[g][0] = m1[g][1] = ~0ull; m2[g][0] = m2[g][1] = ~0ull; }

    const u32 aoff = (u32)((warp_m * 64 + (lane & 15)) * 528 + (lane >> 4) * 16);
    const u32 boff = (u32)(((lane & 7) + (lane >> 4) * 8) * 144 + ((lane >> 3) & 1) * 16
                           + warp_n * 4608);

    for (int g = 0; g < 96; g++) {
        int tile = g / 12, s = g - tile * 12;
        int pass = s >> 2, c = s & 3;
        int buf = g & 1;
        uint4 pf[4];
        const bool more = (g + 1) < 96;
        if (more) {
            const uint4* src = region_ptr(g + 1);
            #pragma unroll
            for (int j = 0; j < 4; j++) pf[j] = src[j * 256 + tid];
        }
        const u32 abase = sb + (u32)((pass == 1) ? SM_ALO : SM_AHI) + aoff + (u32)(c * 128);
        const u32 bbase = sb + SM_BBUF + (u32)(buf * 18432) + boff;
        #pragma unroll
        for (int ks = 0; ks < 4; ks++) {
            u32 af[4][4], bfr[2][4];
            #pragma unroll
            for (int gi = 0; gi < 4; gi++)
                LDSM4(af[gi][0], af[gi][1], af[gi][2], af[gi][3],
                      abase + gi * 8448 + ks * 32);
            #pragma unroll
            for (int n2 = 0; n2 < 2; n2++)
                LDSM4(bfr[n2][0], bfr[n2][1], bfr[n2][2], bfr[n2][3],
                      bbase + n2 * 2304 + ks * 32);
            #pragma unroll
            for (int gi = 0; gi < 4; gi++)
                #pragma unroll
                for (int nf = 0; nf < 4; nf++)
                    MMA16816(acc[gi][nf][0], acc[gi][nf][1], acc[gi][nf][2], acc[gi][nf][3],
                             af[gi][0], af[gi][1], af[gi][2], af[gi][3],
                             bfr[nf >> 1][(nf & 1) * 2], bfr[nf >> 1][(nf & 1) * 2 + 1]);
        }
        if (s == 11) {
            // epilogue for this tile: d = fl(fl(A+B) - 2*dot), top-2 per row
            const int tbase = tile * 128 + warp_n * 32;
            #pragma unroll
            for (int nf = 0; nf < 4; nf++) {
                const int sym0 = tbase + nf * 8 + (lane & 3) * 2;
                const float w0 = g_wnorm[sym0];
                const float w1 = g_wnorm[sym0 + 1];
                #pragma unroll
                for (int gi = 0; gi < 4; gi++) {
                    #pragma unroll
                    for (int h = 0; h < 2; h++) {
                        float d0 = __fmaf_rn(-2.f, acc[gi][nf][h * 2],
                                             __fadd_rn(a_r[gi][h], w0));
                        float d1 = __fmaf_rn(-2.f, acc[gi][nf][h * 2 + 1],
                                             __fadd_rn(a_r[gi][h], w1));
                        u64 k0 = ((u64)__float_as_uint(d0) << 32) | (u32)sym0;
                        u64 k1 = ((u64)__float_as_uint(d1) << 32) | (u32)(sym0 + 1);
                        if (k0 < m1[gi][h]) { m2[gi][h] = m1[gi][h]; m1[gi][h] = k0; }
                        else if (k0 < m2[gi][h]) m2[gi][h] = k0;
                        if (k1 < m1[gi][h]) { m2[gi][h] = m1[gi][h]; m1[gi][h] = k1; }
                        else if (k1 < m2[gi][h]) m2[gi][h] = k1;
                        acc[gi][nf][h * 2] = 0.f;
                        acc[gi][nf][h * 2 + 1] = 0.f;
                    }
                }
            }
        }
        __syncthreads();
        if (more) {
            char* dst = smem + SM_BBUF + (buf ^ 1) * 18432;
            #pragma unroll
            for (int j = 0; j < 4; j++) {
                int idx = j * 256 + tid, sym = idx >> 3, seg = idx & 7;
                *(uint4*)(dst + sym * 144 + seg * 16) = pf[j];
            }
        }
        __syncthreads();
    }

    // ---- cross-thread top-2 merge per pixel row ----
    u64* red2 = (u64*)(smem + SM_RED);
    const int slot = warp_n * 4 + (lane & 3);
    #pragma unroll
    for (int gi = 0; gi < 4; gi++)
        #pragma unroll
        for (int h = 0; h < 2; h++) {
            int row = warp_m * 64 + gi * 16 + (lane >> 2) + h * 8;
            red2[(row * 16 + slot) * 2]     = m1[gi][h];
            red2[(row * 16 + slot) * 2 + 1] = m2[gi][h];
        }
    __syncthreads();
    if (tid < 128) {
        u64 b1 = ~0ull, b2 = ~0ull;
        #pragma unroll
        for (int t = 0; t < 16; t++) {
            u64 x1 = red2[(tid * 16 + t) * 2];
            u64 x2 = red2[(tid * 16 + t) * 2 + 1];
            if (x1 < b1) { u64 c2 = (b1 < x2) ? b1 : x2; b1 = x1; b2 = (c2 < b2) ? c2 : b2; }
            else if (x1 < b2) b2 = x1;
        }
        if (p0 + tid < npix) {
            g_code[p0 + tid] = (int)(u32)b1;
            float d1 = __uint_as_float((u32)(b1 >> 32));
            float d2 = __uint_as_float((u32)(b2 >> 32));
            if (!(d2 - d1 > MARGIN)) {
                int fs = atomicAdd(&g_flagcnt, 1);
                g_flaglist[fs] = p0 + tid;
            }
        }
    }
}

// ================= fixup: exact sequential-chain rescore of flagged pixels ==========
#define FX_WCH 0
#define FX_XR  65792
#define FX_PP  69888
#define FX_A   70912
#define FX_BB  70928
#define FX_TOT 72976

__global__ void __launch_bounds__(256, 1)
fixup_kernel(const float* __restrict__ X, const float* __restrict__ W)
{
    float* wch = (float*)(smem + FX_WCH);   // [64][257]
    float* xr  = (float*)(smem + FX_XR);    // [4][256]
    float* pp  = (float*)(smem + FX_PP);    // [4][64]
    float* Aa  = (float*)(smem + FX_A);     // [4]
    u64*   bb  = (u64*)(smem + FX_BB);      // [4][64]
    const int tid = threadIdx.x;
    const int pix = tid >> 6, li = tid & 63;
    const int cnt = g_flagcnt;

    for (int gidx = blockIdx.x; gidx * 4 < cnt; gidx += gridDim.x) {
        int fslot = gidx * 4 + pix;
        bool act = fslot < cnt;
        int pixel = act ? g_flaglist[fslot] : 0;
        float4 xv = make_float4(0.f, 0.f, 0.f, 0.f);
        if (act) xv = ((const float4*)X)[(size_t)pixel * 64 + li];
        xr[pix * 256 + li * 4 + 0] = xv.x;
        xr[pix * 256 + li * 4 + 1] = xv.y;
        xr[pix * 256 + li * 4 + 2] = xv.z;
        xr[pix * 256 + li * 4 + 3] = xv.w;
        pp[pix * 64 + li] = ((xv.x * xv.x + xv.y * xv.y) + xv.z * xv.z) + xv.w * xv.w;
        __syncthreads();
        if (li == 0) {
            float a = 0.f;
            #pragma unroll
            for (int kq = 0; kq < 64; kq++) a += pp[pix * 64 + kq];
            Aa[pix] = a;
        }
        u64 best = ~0ull;
        for (int c = 0; c < 16; c++) {
            __syncthreads();
            #pragma unroll
            for (int i = 0; i < 16; i++) {
                int q = i * 256 + tid;
                int sym = q >> 6, kq = q & 63;
                float4 wv = ((const float4*)W)[(size_t)(c * 64 + sym) * 64 + kq];
                wch[sym * 257 + kq * 4 + 0] = wv.x;
                wch[sym * 257 + kq * 4 + 1] = wv.y;
                wch[sym * 257 + kq * 4 + 2] = wv.z;
                wch[sym * 257 + kq * 4 + 3] = wv.w;
            }
            __syncthreads();
            if (act) {
                const float* wr = wch + li * 257;
                const float* xp = xr + pix * 256;
                float accd = 0.f;
                #pragma unroll 8
                for (int k = 0; k < 256; k++) accd = __fmaf_rn(xp[k], wr[k], accd);
                int sidx = c * 64 + li;
                float d = __fmaf_rn(-2.f, accd, __fadd_rn(Aa[pix], g_wnorm[sidx]));
                u64 key = ((u64)__float_as_uint(d) << 32) | (u32)sidx;
                if (key < best) best = key;
            }
        }
        bb[pix * 64 + li] = best;
        __syncthreads();
        if (li == 0 && act) {
            u64 b = bb[pix * 64];
            for (int i = 1; i < 64; i++) if (bb[pix * 64 + i] < b) b = bb[pix * 64 + i];
            g_code[pixel] = (int)(u32)b;
        }
        __syncthreads();
    }
}

// ================= gather + deviation ===============================================
__global__ void gather_kernel(const float* __restrict__ X, const float* __restrict__ W,
                              float* __restrict__ out, int npix, long long out_cap)
{
    __shared__ float psum[256];
    __shared__ int codes[128];
    const int tid = threadIdx.x;
    const int p0 = blockIdx.x * 128;
    if (tid < 128) codes[tid] = (p0 + tid < npix) ? g_code[p0 + tid] : 0;
    __syncthreads();
    const float4* Xg4 = (const float4*)X;
    const float4* Wg4 = (const float4*)W;
    float4* out4 = (float4*)out;
    float dsum = 0.f;
    #pragma unroll 4
    for (int i = 0; i < 32; i++) {
        int q = i * 256 + tid, row = q >> 6, kq = q & 63;
        long long gp = p0 + row;
        if (gp < npix) {
            int c = codes[row];
            float4 wv = Wg4[(size_t)c * 64 + kq];
            float4 xv = Xg4[gp * 64 + kq];
            float t0 = wv.x - xv.x, t1 = wv.y - xv.y;
            float t2 = wv.z - xv.z, t3 = wv.w - xv.w;
            float4 ov;
            ov.x = xv.x + t0; ov.y = xv.y + t1; ov.z = xv.z + t2; ov.w = xv.w + t3;
            long long e = gp * 64 + kq;
            if (e * 4 + 3 < out_cap) out4[e] = ov;
            dsum += t0 * t0 + t1 * t1 + t2 * t2 + t3 * t3;
        }
    }
    psum[tid] = dsum;
    __syncthreads();
    #pragma unroll
    for (int sft = 128; sft > 0; sft >>= 1) {
        if (tid < sft) psum[tid] += psum[tid + sft];
        __syncthreads();
    }
    if (tid == 0) atomicAdd(&g_devsum, (double)psum[0]);
}

__global__ void final_kernel(float* out, long long n, long long out_size) {
    double dev = 1.25 * g_devsum / (double)n;
    for (long long i = n + threadIdx.x; i < out_size; i += blockDim.x)
        out[i] = (float)dev;
}

// ================= launch ===========================================================
extern "C" void kernel_launch(void* const* d_in, const int* in_sizes, int n_in,
                              void* d_out, int out_size) {
    const float* X = (const float*)d_in[0];
    const float* W = (const float*)d_in[1];
    float* out = (float*)d_out;
    const int npix = in_sizes[0] / 256;
    const int S = in_sizes[1] / 256;

    cudaFuncSetAttribute(vq_kernel, cudaFuncAttributeMaxDynamicSharedMemorySize, SM_TOTAL);
    cudaFuncSetAttribute(fixup_kernel, cudaFuncAttributeMaxDynamicSharedMemorySize, FX_TOT);

    prep_kernel<<<S, 256>>>(W);
    vq_kernel<<<(npix + 127) / 128, 256, SM_TOTAL>>>(X, npix);
    fixup_kernel<<<256, 256, FX_TOT>>>(X, W);
    gather_kernel<<<(npix + 127) / 128, 256>>>(X, W, out, npix, (long long)out_size);
    final_kernel<<<1, 256>>>(out, (long long)npix * 256, (long long)out_size);
}

// round 6
// speedup vs baseline: 1.5776x; 1.3169x over previous
#include <cuda_runtime.h>
#include <cuda_fp16.h>
#include <cstdint>

typedef unsigned long long u64;
typedef uint32_t u32;

__device__ double g_devsum;
__device__ int    g_flagcnt;
__device__ u32    g_wmaxb;          // zero-init; monotone atomicMax -> replay-deterministic
__device__ float  g_wnorm[1024];
__device__ int    g_code[65536];
__device__ int    g_flaglist[65536];
// [tile8][chunk4] regions of 16KB: [sym128][k64] fp16 (w scaled by 1024)
__device__ __align__(16) unsigned char g_wblob[32 * 16384];

__device__ __forceinline__ u32 smem_to_u32(const void* p) {
    u32 a;
    asm("{ .reg .u64 t; cvta.to.shared.u64 t, %1; cvt.u32.u64 %0, t; }" : "=r"(a) : "l"(p));
    return a;
}

#define LDSM4(r0, r1, r2, r3, addr) \
    asm volatile("ldmatrix.sync.aligned.m8n8.x4.shared.b16 {%0,%1,%2,%3}, [%4];" \
                 : "=r"(r0), "=r"(r1), "=r"(r2), "=r"(r3) : "r"(addr))

#define MMA16816(c0, c1, c2, c3, a0, a1, a2, a3, b0, b1) \
    asm volatile("mma.sync.aligned.m16n8k16.row.col.f32.f16.f16.f32 " \
                 "{%0,%1,%2,%3},{%4,%5,%6,%7},{%8,%9},{%0,%1,%2,%3};" \
                 : "+f"(c0), "+f"(c1), "+f"(c2), "+f"(c3) \
                 : "r"(a0), "r"(a1), "r"(a2), "r"(a3), "r"(b0), "r"(b1))

// ================= prep: wnorm + wmax + fp16 W blob (scaled 1024) ===================
__global__ void prep_kernel(const float* __restrict__ W) {
    int s = blockIdx.x, tid = threadIdx.x;
    __shared__ float red[8], redm[8];
    float v = W[s * 256 + tid];
    float acc = v * v;
    float am = fabsf(v);
    #pragma unroll
    for (int o = 16; o; o >>= 1) {
        acc += __shfl_xor_sync(0xffffffffu, acc, o);
        am = fmaxf(am, __shfl_xor_sync(0xffffffffu, am, o));
    }
    if ((tid & 31) == 0) { red[tid >> 5] = acc; redm[tid >> 5] = am; }
    __syncthreads();
    if (tid == 0) {
        float t = 0.f, m = 0.f;
        #pragma unroll
        for (int i = 0; i < 8; i++) { t += red[i]; m = fmaxf(m, redm[i]); }
        g_wnorm[s] = t;
        atomicMax(&g_wmaxb, __float_as_uint(m));
        if (s == 0) { g_devsum = 0.0; g_flagcnt = 0; }
    }
    int tile = s >> 7, sym = s & 127, c = tid >> 6, k = tid & 63;
    __half h = __float2half(v * 1024.0f);    // *1024 exact; RN to fp16
    *(__half*)(g_wblob + (size_t)(tile * 4 + c) * 16384 + sym * 128 + k * 2) = h;
}

// ================= vq: single fp16 HMMA GEMM + certified-margin argmin ==============
#define SM_A     0          // 128 x 264 fp16 (stride 528B) = 67584
#define SM_BBUF  67584      // 2 x 18432 (128 syms x 72 fp16, stride 144B)
#define SM_PART  104448     // 128 x 65 floats (33280) ; RED overlays here later
#define SM_RED   104448     // 128 x 16 x 2 u64 = 32768
#define SM_PART2 137728     // 128 x 65 floats (33280)
#define SM_AROW  171008     // 128 floats
#define SM_SABS  171520     // 128 floats
#define SM_TOTAL 172032

extern __shared__ char smem[];

__global__ void __launch_bounds__(256, 1)
vq_kernel(const float* __restrict__ X, int npix)
{
    const int tid = threadIdx.x, lane = tid & 31, wid = tid >> 5;
    const int warp_m = wid & 1, warp_n = wid >> 1;
    const int p0 = blockIdx.x * 128;
    const u32 sb = smem_to_u32(smem);

    // ---- phase 0: X -> fp16 A smem + x^2 and |x| quad partials ----
    float* part  = (float*)(smem + SM_PART);
    float* part2 = (float*)(smem + SM_PART2);
    const float4* Xg4 = (const float4*)X;
    #pragma unroll 4
    for (int i = 0; i < 32; i++) {
        int q = i * 256 + tid, row = q >> 6, kq = q & 63;
        float4 v = make_float4(0.f, 0.f, 0.f, 0.f);
        if (p0 + row < npix) v = Xg4[(size_t)(p0 + row) * 64 + kq];
        __half h0 = __float2half(v.x), h1 = __float2half(v.y);
        __half h2 = __float2half(v.z), h3 = __float2half(v.w);
        u32 hx = (u32)__half_as_ushort(h0) | ((u32)__half_as_ushort(h1) << 16);
        u32 hy = (u32)__half_as_ushort(h2) | ((u32)__half_as_ushort(h3) << 16);
        *(uint2*)(smem + SM_A + row * 528 + kq * 8) = make_uint2(hx, hy);
        part[row * 65 + kq]  = ((v.x * v.x + v.y * v.y) + v.z * v.z) + v.w * v.w;
        part2[row * 65 + kq] = ((fabsf(v.x) + fabsf(v.y)) + fabsf(v.z)) + fabsf(v.w);
    }
    __syncthreads();
    float* arow = (float*)(smem + SM_AROW);
    float* sabs = (float*)(smem + SM_SABS);
    if (tid < 128) {
        float a = 0.f, s = 0.f;
        #pragma unroll
        for (int kq = 0; kq < 64; kq++) { a += part[tid * 65 + kq]; s += part2[tid * 65 + kq]; }
        arow[tid] = a;
        sabs[tid] = s;
    }
    __syncthreads();
    float a_r[4][2];
    #pragma unroll
    for (int g = 0; g < 4; g++)
        #pragma unroll
        for (int h = 0; h < 2; h++)
            a_r[g][h] = arow[warp_m * 64 + g * 16 + (lane >> 2) + h * 8];
    __syncthreads();

    // ---- fill B chunk 0 ----
    {
        const uint4* src = (const uint4*)g_wblob;
        #pragma unroll
        for (int j = 0; j < 4; j++) {
            int idx = j * 256 + tid, sym = idx >> 3, seg = idx & 7;
            *(uint4*)(smem + SM_BBUF + sym * 144 + seg * 16) = src[idx];
        }
    }
    __syncthreads();

    float acc[4][4][4];
    #pragma unroll
    for (int g = 0; g < 4; g++)
        #pragma unroll
        for (int n = 0; n < 4; n++)
            #pragma unroll
            for (int j = 0; j < 4; j++) acc[g][n][j] = 0.f;
    u64 m1[4][2], m2[4][2];
    #pragma unroll
    for (int g = 0; g < 4; g++) { m1[g][0] = m1[g][1] = ~0ull; m2[g][0] = m2[g][1] = ~0ull; }

    const u32 aoff = (u32)((warp_m * 64 + (lane & 15)) * 528 + (lane >> 4) * 16);
    const u32 boff = (u32)(((lane & 7) + (lane >> 4) * 8) * 144 + ((lane >> 3) & 1) * 16
                           + warp_n * 4608);

    for (int g = 0; g < 32; g++) {
        const int tile = g >> 2, c = g & 3, buf = g & 1;
        uint4 pf[4];
        const bool more = (g + 1) < 32;
        if (more) {
            const uint4* src = (const uint4*)(g_wblob + (size_t)(g + 1) * 16384);
            #pragma unroll
            for (int j = 0; j < 4; j++) pf[j] = src[j * 256 + tid];
        }
        const u32 abase = sb + SM_A + aoff + (u32)(c * 128);
        const u32 bbase = sb + SM_BBUF + (u32)(buf * 18432) + boff;
        #pragma unroll
        for (int ks = 0; ks < 4; ks++) {
            u32 af[4][4], bfr[2][4];
            #pragma unroll
            for (int gi = 0; gi < 4; gi++)
                LDSM4(af[gi][0], af[gi][1], af[gi][2], af[gi][3],
                      abase + gi * 8448 + ks * 32);
            #pragma unroll
            for (int n2 = 0; n2 < 2; n2++)
                LDSM4(bfr[n2][0], bfr[n2][1], bfr[n2][2], bfr[n2][3],
                      bbase + n2 * 2304 + ks * 32);
            #pragma unroll
            for (int gi = 0; gi < 4; gi++)
                #pragma unroll
                for (int nf = 0; nf < 4; nf++)
                    MMA16816(acc[gi][nf][0], acc[gi][nf][1], acc[gi][nf][2], acc[gi][nf][3],
                             af[gi][0], af[gi][1], af[gi][2], af[gi][3],
                             bfr[nf >> 1][(nf & 1) * 2], bfr[nf >> 1][(nf & 1) * 2 + 1]);
        }
        if (c == 3) {
            // d = fl(fl(A+B) - 2*(acc/1024)) ; -2/1024 = -2^-9 exact inside fma
            const int tbase = tile * 128 + warp_n * 32;
            #pragma unroll
            for (int nf = 0; nf < 4; nf++) {
                const int sym0 = tbase + nf * 8 + (lane & 3) * 2;
                const float w0 = g_wnorm[sym0];
                const float w1 = g_wnorm[sym0 + 1];
                #pragma unroll
                for (int gi = 0; gi < 4; gi++) {
                    #pragma unroll
                    for (int h = 0; h < 2; h++) {
                        float d0 = __fmaf_rn(-0.001953125f, acc[gi][nf][h * 2],
                                             __fadd_rn(a_r[gi][h], w0));
                        float d1 = __fmaf_rn(-0.001953125f, acc[gi][nf][h * 2 + 1],
                                             __fadd_rn(a_r[gi][h], w1));
                        u64 k0 = ((u64)__float_as_uint(d0) << 32) | (u32)sym0;
                        u64 k1 = ((u64)__float_as_uint(d1) << 32) | (u32)(sym0 + 1);
                        if (k0 < m1[gi][h]) { m2[gi][h] = m1[gi][h]; m1[gi][h] = k0; }
                        else if (k0 < m2[gi][h]) m2[gi][h] = k0;
                        if (k1 < m1[gi][h]) { m2[gi][h] = m1[gi][h]; m1[gi][h] = k1; }
                        else if (k1 < m2[gi][h]) m2[gi][h] = k1;
                        acc[gi][nf][h * 2] = 0.f;
                        acc[gi][nf][h * 2 + 1] = 0.f;
                    }
                }
            }
        }
        __syncthreads();
        if (more) {
            char* dst = smem + SM_BBUF + (buf ^ 1) * 18432;
            #pragma unroll
            for (int j = 0; j < 4; j++) {
                int idx = j * 256 + tid, sym = idx >> 3, seg = idx & 7;
                *(uint4*)(dst + sym * 144 + seg * 16) = pf[j];
            }
        }
        __syncthreads();
    }

    // ---- top-2 merge + per-pixel certified margin ----
    u64* red2 = (u64*)(smem + SM_RED);
    const int slot = warp_n * 4 + (lane & 3);
    #pragma unroll
    for (int gi = 0; gi < 4; gi++)
        #pragma unroll
        for (int h = 0; h < 2; h++) {
            int row = warp_m * 64 + gi * 16 + (lane >> 2) + h * 8;
            red2[(row * 16 + slot) * 2]     = m1[gi][h];
            red2[(row * 16 + slot) * 2 + 1] = m2[gi][h];
        }
    __syncthreads();
    if (tid < 128) {
        u64 b1 = ~0ull, b2 = ~0ull;
        #pragma unroll
        for (int t = 0; t < 16; t++) {
            u64 x1 = red2[(tid * 16 + t) * 2];
            u64 x2 = red2[(tid * 16 + t) * 2 + 1];
            if (x1 < b1) { u64 c2 = (b1 < x2) ? b1 : x2; b1 = x1; b2 = (c2 < b2) ? c2 : b2; }
            else if (x1 < b2) b2 = x1;
        }
        if (p0 + tid < npix) {
            g_code[p0 + tid] = (int)(u32)b1;
            float d1 = __uint_as_float((u32)(b1 >> 32));
            float d2 = __uint_as_float((u32)(b2 >> 32));
            float wmax = __uint_as_float(g_wmaxb);
            // margin = 2 * (2*Delta_dot + ulp) ; Delta_dot <= sabs*wmax*2^-10 -> 4*Delta = sabs*wmax*2^-8
            float marg = sabs[tid] * wmax * 0.003965f + 1.0e-4f;
            if (!(d2 - d1 > marg)) {
                int fs = atomicAdd(&g_flagcnt, 1);
                g_flaglist[fs] = p0 + tid;
            }
        }
    }
}

// ================= fixup: exact sequential-chain rescore, 32 pixels/CTA =============
#define FX_WCH   0          // 64 x 260 floats = 66560
#define FX_XR    66560      // 32 x 256 floats = 32768
#define FX_PP    99328      // 32 x 64 floats  = 8192
#define FX_AA    107520     // 32 floats
#define FX_BBR   107648     // 4 x 64 u64 = 2048
#define FX_PID   109696     // 32 ints
#define FX_TOT   109824

__global__ void __launch_bounds__(256, 1)
fixup_kernel(const float* __restrict__ X, const float* __restrict__ W)
{
    float* wch = (float*)(smem + FX_WCH);
    float* xr  = (float*)(smem + FX_XR);
    float* pp  = (float*)(smem + FX_PP);
    float* Aa  = (float*)(smem + FX_AA);
    u64*   bbr = (u64*)(smem + FX_BBR);
    int*   pid = (int*)(smem + FX_PID);
    const int tid = threadIdx.x, group = tid >> 6, slane = tid & 63;
    const int cnt = g_flagcnt;

    for (int g = blockIdx.x; g * 32 < cnt; g += gridDim.x) {
        __syncthreads();
        if (tid < 32) pid[tid] = (g * 32 + tid < cnt) ? g_flaglist[g * 32 + tid] : -1;
        __syncthreads();
        #pragma unroll
        for (int i = 0; i < 8; i++) {
            int idx = i * 256 + tid, px = idx >> 6, li = idx & 63;
            int pixel = pid[px];
            float4 xv = make_float4(0.f, 0.f, 0.f, 0.f);
            if (pixel >= 0) xv = ((const float4*)X)[(size_t)pixel * 64 + li];
            *(float4*)(xr + px * 256 + li * 4) = xv;
            pp[px * 64 + li] = ((xv.x * xv.x + xv.y * xv.y) + xv.z * xv.z) + xv.w * xv.w;
        }
        __syncthreads();
        if (tid < 32) {
            float a = 0.f;
            #pragma unroll
            for (int k = 0; k < 64; k++) a += pp[tid * 64 + k];
            Aa[tid] = a;
        }
        u64 best[8];
        #pragma unroll
        for (int j = 0; j < 8; j++) best[j] = ~0ull;

        for (int c = 0; c < 16; c++) {
            __syncthreads();
            #pragma unroll
            for (int i = 0; i < 16; i++) {
                int idx = i * 256 + tid, sym = idx >> 6, kq = idx & 63;
                float4 wv = ((const float4*)W)[(size_t)(c * 64 + sym) * 64 + kq];
                *(float4*)(wch + sym * 260 + kq * 4) = wv;
            }
            __syncthreads();
            const float* wr = wch + slane * 260;
            float acc8[8];
            #pragma unroll
            for (int j = 0; j < 8; j++) acc8[j] = 0.f;
            for (int kq = 0; kq < 64; kq++) {
                float4 w4 = *(const float4*)(wr + kq * 4);
                #pragma unroll
                for (int j = 0; j < 8; j++) {
                    float4 x4 = *(const float4*)(xr + (group * 8 + j) * 256 + kq * 4);
                    acc8[j] = __fmaf_rn(x4.x, w4.x, acc8[j]);
                    acc8[j] = __fmaf_rn(x4.y, w4.y, acc8[j]);
                    acc8[j] = __fmaf_rn(x4.z, w4.z, acc8[j]);
                    acc8[j] = __fmaf_rn(x4.w, w4.w, acc8[j]);
                }
            }
            const int sidx = c * 64 + slane;
            const float wn = g_wnorm[sidx];
            #pragma unroll
            for (int j = 0; j < 8; j++) {
                float d = __fmaf_rn(-2.f, acc8[j], __fadd_rn(Aa[group * 8 + j], wn));
                u64 key = ((u64)__float_as_uint(d) << 32) | (u32)sidx;
                if (key < best[j]) best[j] = key;
            }
        }
        #pragma unroll
        for (int j = 0; j < 8; j++) {
            __syncthreads();
            bbr[group * 64 + slane] = best[j];
            __syncthreads();
            if (slane == 0) {
                int pixel = pid[group * 8 + j];
                if (pixel >= 0) {
                    u64 b = bbr[group * 64];
                    for (int i = 1; i < 64; i++)
                        if (bbr[group * 64 + i] < b) b = bbr[group * 64 + i];
                    g_code[pixel] = (int)(u32)b;
                }
            }
        }
        __syncthreads();
    }
}

// ================= gather + deviation ===============================================
__global__ void gather_kernel(const float* __restrict__ X, const float* __restrict__ W,
                              float* __restrict__ out, int npix, long long out_cap)
{
    __shared__ float psum[256];
    __shared__ int codes[128];
    const int tid = threadIdx.x;
    const int p0 = blockIdx.x * 128;
    if (tid < 128) codes[tid] = (p0 + tid < npix) ? g_code[p0 + tid] : 0;
    __syncthreads();
    const float4* Xg4 = (const float4*)X;
    const float4* Wg4 = (const float4*)W;
    float4* out4 = (float4*)out;
    float dsum = 0.f;
    #pragma unroll 4
    for (int i = 0; i < 32; i++) {
        int q = i * 256 + tid, row = q >> 6, kq = q & 63;
        long long gp = p0 + row;
        if (gp < npix) {
            int c = codes[row];
            float4 wv = Wg4[(size_t)c * 64 + kq];
            float4 xv = Xg4[gp * 64 + kq];
            float t0 = wv.x - xv.x, t1 = wv.y - xv.y;
            float t2 = wv.z - xv.z, t3 = wv.w - xv.w;
            float4 ov;
            ov.x = xv.x + t0; ov.y = xv.y + t1; ov.z = xv.z + t2; ov.w = xv.w + t3;
            long long e = gp * 64 + kq;
            if (e * 4 + 3 < out_cap) out4[e] = ov;
            dsum += t0 * t0 + t1 * t1 + t2 * t2 + t3 * t3;
        }
    }
    psum[tid] = dsum;
    __syncthreads();
    #pragma unroll
    for (int sft = 128; sft > 0; sft >>= 1) {
        if (tid < sft) psum[tid] += psum[tid + sft];
        __syncthreads();
    }
    if (tid == 0) atomicAdd(&g_devsum, (double)psum[0]);
}

__global__ void final_kernel(float* out, long long n, long long out_size) {
    double dev = 1.25 * g_devsum / (double)n;
    for (long long i = n + threadIdx.x; i < out_size; i += blockDim.x)
        out[i] = (float)dev;
}

// ================= launch ===========================================================
extern "C" void kernel_launch(void* const* d_in, const int* in_sizes, int n_in,
                              void* d_out, int out_size) {
    const float* X = (const float*)d_in[0];
    const float* W = (const float*)d_in[1];
    float* out = (float*)d_out;
    const int npix = in_sizes[0] / 256;
    const int S = in_sizes[1] / 256;

    cudaFuncSetAttribute(vq_kernel, cudaFuncAttributeMaxDynamicSharedMemorySize, SM_TOTAL);
    cudaFuncSetAttribute(fixup_kernel, cudaFuncAttributeMaxDynamicSharedMemorySize, FX_TOT);

    prep_kernel<<<S, 256>>>(W);
    vq_kernel<<<(npix + 127) / 128, 256, SM_TOTAL>>>(X, npix);
    fixup_kernel<<<256, 256, FX_TOT>>>(X, W);
    gather_kernel<<<(npix + 127) / 128, 256>>>(X, W, out, npix, (long long)out_size);
    final_kernel<<<1, 256>>>(out, (long long)npix * 256, (long long)out_size);
}

// round 7
// speedup vs baseline: 3.0291x; 1.9201x over previous
#include <cuda_runtime.h>
#include <cuda_fp16.h>
#include <cstdint>

typedef unsigned long long u64;
typedef uint32_t u32;

__device__ double g_devsum;
__device__ int    g_flagcnt;
__device__ u32    g_wmaxb;          // zero-init; monotone atomicMax -> replay-deterministic
__device__ float  g_wnorm[1024];
__device__ int    g_code[65536];
__device__ int    g_flaglist[65536];
// [tile8][chunk4] regions of 16KB: [sym128][k64] fp16 (w scaled by 1024)
__device__ __align__(16) unsigned char g_wblob[32 * 16384];
// approximate scores: r = d_app - A, fp16, [pixel][sym] (2KB per pixel)
__device__ __align__(16) unsigned short g_dstore[65536 * 1024];

__device__ __forceinline__ u32 smem_to_u32(const void* p) {
    u32 a;
    asm("{ .reg .u64 t; cvta.to.shared.u64 t, %1; cvt.u32.u64 %0, t; }" : "=r"(a) : "l"(p));
    return a;
}

#define LDSM4(r0, r1, r2, r3, addr) \
    asm volatile("ldmatrix.sync.aligned.m8n8.x4.shared.b16 {%0,%1,%2,%3}, [%4];" \
                 : "=r"(r0), "=r"(r1), "=r"(r2), "=r"(r3) : "r"(addr))

#define MMA16816(c0, c1, c2, c3, a0, a1, a2, a3, b0, b1) \
    asm volatile("mma.sync.aligned.m16n8k16.row.col.f32.f16.f16.f32 " \
                 "{%0,%1,%2,%3},{%4,%5,%6,%7},{%8,%9},{%0,%1,%2,%3};" \
                 : "+f"(c0), "+f"(c1), "+f"(c2), "+f"(c3) \
                 : "r"(a0), "r"(a1), "r"(a2), "r"(a3), "r"(b0), "r"(b1))

#define CP_ASYNC16(dst, src) \
    asm volatile("cp.async.cg.shared.global [%0], [%1], 16;" :: "r"(dst), "l"(src))
#define CP_COMMIT() asm volatile("cp.async.commit_group;")
#define CP_WAIT1()  asm volatile("cp.async.wait_group 1;")
#define CP_WAIT0()  asm volatile("cp.async.wait_group 0;")

// ================= prep: wnorm + wmax + fp16 W blob (scaled 1024) ===================
__global__ void prep_kernel(const float* __restrict__ W) {
    int s = blockIdx.x, tid = threadIdx.x;
    __shared__ float red[8], redm[8];
    float v = W[s * 256 + tid];
    float acc = v * v;
    float am = fabsf(v);
    #pragma unroll
    for (int o = 16; o; o >>= 1) {
        acc += __shfl_xor_sync(0xffffffffu, acc, o);
        am = fmaxf(am, __shfl_xor_sync(0xffffffffu, am, o));
    }
    if ((tid & 31) == 0) { red[tid >> 5] = acc; redm[tid >> 5] = am; }
    __syncthreads();
    if (tid == 0) {
        float t = 0.f, m = 0.f;
        #pragma unroll
        for (int i = 0; i < 8; i++) { t += red[i]; m = fmaxf(m, redm[i]); }
        g_wnorm[s] = t;
        atomicMax(&g_wmaxb, __float_as_uint(m));
        if (s == 0) { g_devsum = 0.0; g_flagcnt = 0; }
    }
    int tile = s >> 7, sym = s & 127, c = tid >> 6, k = tid & 63;
    __half h = __float2half(v * 1024.0f);
    *(__half*)(g_wblob + (size_t)(tile * 4 + c) * 16384 + sym * 128 + k * 2) = h;
}

// ================= vq: single fp16 HMMA GEMM + margin argmin + d-store ==============
#define SM_A     0          // 128 x 264 fp16 (stride 528B) = 67584
#define SM_BBUF  67584      // 2 x 18432 (128 syms x 72 fp16, stride 144B)
#define SM_PART  104448     // 128 x 65 floats ; RED overlays here later
#define SM_RED   104448     // 128 x 16 x 2 u64 = 32768
#define SM_PART2 137728     // 128 x 65 floats
#define SM_AROW  171008     // 128 floats
#define SM_SABS  171520     // 128 floats
#define SM_TOTAL 172032

extern __shared__ char smem[];

__global__ void __launch_bounds__(256, 1)
vq_kernel(const float* __restrict__ X, int npix)
{
    const int tid = threadIdx.x, lane = tid & 31, wid = tid >> 5;
    const int warp_m = wid & 1, warp_n = wid >> 1;
    const int p0 = blockIdx.x * 128;
    const u32 sb = smem_to_u32(smem);

    // ---- phase 0: X -> fp16 A smem + x^2 and |x| quad partials ----
    float* part  = (float*)(smem + SM_PART);
    float* part2 = (float*)(smem + SM_PART2);
    const float4* Xg4 = (const float4*)X;
    #pragma unroll 4
    for (int i = 0; i < 32; i++) {
        int q = i * 256 + tid, row = q >> 6, kq = q & 63;
        float4 v = make_float4(0.f, 0.f, 0.f, 0.f);
        if (p0 + row < npix) v = Xg4[(size_t)(p0 + row) * 64 + kq];
        __half h0 = __float2half(v.x), h1 = __float2half(v.y);
        __half h2 = __float2half(v.z), h3 = __float2half(v.w);
        u32 hx = (u32)__half_as_ushort(h0) | ((u32)__half_as_ushort(h1) << 16);
        u32 hy = (u32)__half_as_ushort(h2) | ((u32)__half_as_ushort(h3) << 16);
        *(uint2*)(smem + SM_A + row * 528 + kq * 8) = make_uint2(hx, hy);
        part[row * 65 + kq]  = ((v.x * v.x + v.y * v.y) + v.z * v.z) + v.w * v.w;
        part2[row * 65 + kq] = ((fabsf(v.x) + fabsf(v.y)) + fabsf(v.z)) + fabsf(v.w);
    }
    __syncthreads();
    float* arow = (float*)(smem + SM_AROW);
    float* sabs = (float*)(smem + SM_SABS);
    if (tid < 128) {
        float a = 0.f, s = 0.f;
        #pragma unroll
        for (int kq = 0; kq < 64; kq++) { a += part[tid * 65 + kq]; s += part2[tid * 65 + kq]; }
        arow[tid] = a;
        sabs[tid] = s;
    }
    __syncthreads();
    float a_r[4][2];
    #pragma unroll
    for (int g = 0; g < 4; g++)
        #pragma unroll
        for (int h = 0; h < 2; h++)
            a_r[g][h] = arow[warp_m * 64 + g * 16 + (lane >> 2) + h * 8];
    __syncthreads();

    // ---- async B pipeline ----
    auto issue_copy = [&](int g, int buf) {
        #pragma unroll
        for (int j = 0; j < 4; j++) {
            int idx = j * 256 + tid, sym = idx >> 3, seg = idx & 7;
            u32 dst = sb + SM_BBUF + (u32)(buf * 18432 + sym * 144 + seg * 16);
            const char* src = (const char*)g_wblob + (size_t)g * 16384 + (size_t)idx * 16;
            CP_ASYNC16(dst, src);
        }
        CP_COMMIT();
    };
    issue_copy(0, 0);
    issue_copy(1, 1);

    float acc[4][4][4];
    #pragma unroll
    for (int g = 0; g < 4; g++)
        #pragma unroll
        for (int n = 0; n < 4; n++)
            #pragma unroll
            for (int j = 0; j < 4; j++) acc[g][n][j] = 0.f;
    u64 m1[4][2], m2[4][2];
    #pragma unroll
    for (int g = 0; g < 4; g++) { m1[g][0] = m1[g][1] = ~0ull; m2[g][0] = m2[g][1] = ~0ull; }

    const u32 aoff = (u32)((warp_m * 64 + (lane & 15)) * 528 + (lane >> 4) * 16);
    const u32 boff = (u32)(((lane & 7) + (lane >> 4) * 8) * 144 + ((lane >> 3) & 1) * 16
                           + warp_n * 4608);

    for (int g = 0; g < 32; g++) {
        const int tile = g >> 2, c = g & 3, buf = g & 1;
        if (g == 31) { CP_WAIT0(); } else { CP_WAIT1(); }
        __syncthreads();
        const u32 abase = sb + SM_A + aoff + (u32)(c * 128);
        const u32 bbase = sb + SM_BBUF + (u32)(buf * 18432) + boff;
        #pragma unroll
        for (int ks = 0; ks < 4; ks++) {
            u32 af[4][4], bfr[2][4];
            #pragma unroll
            for (int gi = 0; gi < 4; gi++)
                LDSM4(af[gi][0], af[gi][1], af[gi][2], af[gi][3],
                      abase + gi * 8448 + ks * 32);
            #pragma unroll
            for (int n2 = 0; n2 < 2; n2++)
                LDSM4(bfr[n2][0], bfr[n2][1], bfr[n2][2], bfr[n2][3],
                      bbase + n2 * 2304 + ks * 32);
            #pragma unroll
            for (int gi = 0; gi < 4; gi++)
                #pragma unroll
                for (int nf = 0; nf < 4; nf++)
                    MMA16816(acc[gi][nf][0], acc[gi][nf][1], acc[gi][nf][2], acc[gi][nf][3],
                             af[gi][0], af[gi][1], af[gi][2], af[gi][3],
                             bfr[nf >> 1][(nf & 1) * 2], bfr[nf >> 1][(nf & 1) * 2 + 1]);
        }
        if (c == 3) {
            // d = fl(fl(A+B) - 2*(acc/1024)) ; -2^-9 exact in fma.  Also store r = d - A.
            const int tbase = tile * 128 + warp_n * 32;
            #pragma unroll
            for (int nf = 0; nf < 4; nf++) {
                const int sym0 = tbase + nf * 8 + (lane & 3) * 2;
                const float w0 = g_wnorm[sym0];
                const float w1 = g_wnorm[sym0 + 1];
                #pragma unroll
                for (int gi = 0; gi < 4; gi++) {
                    #pragma unroll
                    for (int h = 0; h < 2; h++) {
                        const int row = warp_m * 64 + gi * 16 + (lane >> 2) + h * 8;
                        float d0 = __fmaf_rn(-0.001953125f, acc[gi][nf][h * 2],
                                             __fadd_rn(a_r[gi][h], w0));
                        float d1 = __fmaf_rn(-0.001953125f, acc[gi][nf][h * 2 + 1],
                                             __fadd_rn(a_r[gi][h], w1));
                        if (p0 + row < npix) {
                            __half2 rp = __floats2half2_rn(__fsub_rn(d0, a_r[gi][h]),
                                                           __fsub_rn(d1, a_r[gi][h]));
                            *(u32*)(g_dstore + (size_t)(p0 + row) * 1024 + sym0) =
                                *(u32*)&rp;
                        }
                        u64 k0 = ((u64)__float_as_uint(d0) << 32) | (u32)sym0;
                        u64 k1 = ((u64)__float_as_uint(d1) << 32) | (u32)(sym0 + 1);
                        if (k0 < m1[gi][h]) { m2[gi][h] = m1[gi][h]; m1[gi][h] = k0; }
                        else if (k0 < m2[gi][h]) m2[gi][h] = k0;
                        if (k1 < m1[gi][h]) { m2[gi][h] = m1[gi][h]; m1[gi][h] = k1; }
                        else if (k1 < m2[gi][h]) m2[gi][h] = k1;
                        acc[gi][nf][h * 2] = 0.f;
                        acc[gi][nf][h * 2 + 1] = 0.f;
                    }
                }
            }
        }
        __syncthreads();
        if (g + 2 < 32) issue_copy(g + 2, buf);
    }

    // ---- top-2 merge + per-pixel certified margin ----
    u64* red2 = (u64*)(smem + SM_RED);
    const int slot = warp_n * 4 + (lane & 3);
    #pragma unroll
    for (int gi = 0; gi < 4; gi++)
        #pragma unroll
        for (int h = 0; h < 2; h++) {
            int row = warp_m * 64 + gi * 16 + (lane >> 2) + h * 8;
            red2[(row * 16 + slot) * 2]     = m1[gi][h];
            red2[(row * 16 + slot) * 2 + 1] = m2[gi][h];
        }
    __syncthreads();
    if (tid < 128) {
        u64 b1 = ~0ull, b2 = ~0ull;
        #pragma unroll
        for (int t = 0; t < 16; t++) {
            u64 x1 = red2[(tid * 16 + t) * 2];
            u64 x2 = red2[(tid * 16 + t) * 2 + 1];
            if (x1 < b1) { u64 c2 = (b1 < x2) ? b1 : x2; b1 = x1; b2 = (c2 < b2) ? c2 : b2; }
            else if (x1 < b2) b2 = x1;
        }
        if (p0 + tid < npix) {
            g_code[p0 + tid] = (int)(u32)b1;
            float d1 = __uint_as_float((u32)(b1 >> 32));
            float d2 = __uint_as_float((u32)(b2 >> 32));
            float wmax = __uint_as_float(g_wmaxb);
            float marg = sabs[tid] * wmax * 0.003965f + 1.0e-4f;
            if (!(d2 - d1 > marg)) {
                int fs = atomicAdd(&g_flagcnt, 1);
                g_flaglist[fs] = p0 + tid;
            }
        }
    }
}

// ================= candfix: exact rescore of CANDIDATES only ========================
__device__ __forceinline__ u64 chain_key(const float* xr, const float* __restrict__ W,
                                         int sym, float A) {
    const float4* wp = (const float4*)(W + (size_t)sym * 256);
    float acc = 0.f;
    #pragma unroll 8
    for (int k = 0; k < 64; k++) {
        float4 w4 = __ldg(&wp[k]);
        float4 x4 = *(const float4*)(xr + k * 4);
        acc = __fmaf_rn(x4.x, w4.x, acc);
        acc = __fmaf_rn(x4.y, w4.y, acc);
        acc = __fmaf_rn(x4.z, w4.z, acc);
        acc = __fmaf_rn(x4.w, w4.w, acc);
    }
    float d = __fmaf_rn(-2.f, acc, __fadd_rn(A, g_wnorm[sym]));
    return ((u64)__float_as_uint(d) << 32) | (u32)sym;
}

__global__ void __launch_bounds__(256, 1)
candfix_kernel(const float* __restrict__ X, const float* __restrict__ W)
{
    __shared__ float xrow[8][256];
    __shared__ float pp[8][64];
    __shared__ int   clist[8][34];
    __shared__ int   scnt[8];
    __shared__ float sA[8];
    const int lane = threadIdx.x & 31, w = threadIdx.x >> 5;
    const int wg = blockIdx.x * 8 + w, nw = gridDim.x * 8;
    const int cnt = g_flagcnt;
    const float wmax = __uint_as_float(g_wmaxb);

    for (int i = wg; i < cnt; i += nw) {
        const int pixel = g_flaglist[i];
        float sabs_l = 0.f;
        #pragma unroll
        for (int j = 0; j < 2; j++) {
            int kq = lane + j * 32;
            float4 v = ((const float4*)X)[(size_t)pixel * 64 + kq];
            *(float4*)&xrow[w][kq * 4] = v;
            pp[w][kq] = ((v.x * v.x + v.y * v.y) + v.z * v.z) + v.w * v.w;
            sabs_l += ((fabsf(v.x) + fabsf(v.y)) + fabsf(v.z)) + fabsf(v.w);
        }
        if (lane == 0) scnt[w] = 0;
        __syncwarp();
        if (lane == 0) {
            float a = 0.f;
            #pragma unroll
            for (int k = 0; k < 64; k++) a += pp[w][k];
            sA[w] = a;
        }
        #pragma unroll
        for (int o = 16; o; o >>= 1) sabs_l += __shfl_xor_sync(0xffffffffu, sabs_l, o);
        __syncwarp();
        const float A = sA[w];

        // pass 1: min of stored r
        const uint4* rrow = (const uint4*)(g_dstore + (size_t)pixel * 1024);
        uint4 rv[4];
        float rmin = 3.4e38f;
        #pragma unroll
        for (int j = 0; j < 4; j++) {
            rv[j] = rrow[lane * 4 + j];
            const u32 wd[4] = {rv[j].x, rv[j].y, rv[j].z, rv[j].w};
            #pragma unroll
            for (int t = 0; t < 4; t++) {
                float2 f = __half22float2(*(const __half2*)&wd[t]);
                rmin = fminf(rmin, fminf(f.x, f.y));
            }
        }
        #pragma unroll
        for (int o = 16; o; o >>= 1)
            rmin = fminf(rmin, __shfl_xor_sync(0xffffffffu, rmin, o));
        const float thr = rmin + sabs_l * wmax * 0.004f + 6.5e-4f;

        // pass 2: collect candidates
        #pragma unroll
        for (int j = 0; j < 4; j++) {
            const u32 wd[4] = {rv[j].x, rv[j].y, rv[j].z, rv[j].w};
            #pragma unroll
            for (int t = 0; t < 4; t++) {
                float2 f = __half22float2(*(const __half2*)&wd[t]);
                int sym = (lane * 16 + j * 4 + t) * 2;
                if (f.x <= thr) {
                    int pos = atomicAdd(&scnt[w], 1);
                    if (pos < 33) clist[w][pos] = sym;
                }
                if (f.y <= thr) {
                    int pos = atomicAdd(&scnt[w], 1);
                    if (pos < 33) clist[w][pos] = sym + 1;
                }
            }
        }
        __syncwarp();
        const int n = scnt[w];
        u64 key = ~0ull;
        if (n <= 32) {
            if (lane < n) key = chain_key(xrow[w], W, clist[w][lane], A);
        } else {
            for (int sym = lane; sym < 1024; sym += 32) {
                u64 k2 = chain_key(xrow[w], W, sym, A);
                if (k2 < key) key = k2;
            }
        }
        #pragma unroll
        for (int o = 16; o; o >>= 1) {
            u64 other = __shfl_xor_sync(0xffffffffu, key, o);
            if (other < key) key = other;
        }
        if (lane == 0) g_code[pixel] = (int)(u32)key;
        __syncwarp();
    }
}

// ================= gather + deviation ===============================================
__global__ void gather_kernel(const float* __restrict__ X, const float* __restrict__ W,
                              float* __restrict__ out, int npix, long long out_cap)
{
    __shared__ float psum[256];
    __shared__ int codes[128];
    const int tid = threadIdx.x;
    const int p0 = blockIdx.x * 128;
    if (tid < 128) codes[tid] = (p0 + tid < npix) ? g_code[p0 + tid] : 0;
    __syncthreads();
    const float4* Xg4 = (const float4*)X;
    const float4* Wg4 = (const float4*)W;
    float4* out4 = (float4*)out;
    float dsum = 0.f;
    #pragma unroll 4
    for (int i = 0; i < 32; i++) {
        int q = i * 256 + tid, row = q >> 6, kq = q & 63;
        long long gp = p0 + row;
        if (gp < npix) {
            int c = codes[row];
            float4 wv = Wg4[(size_t)c * 64 + kq];
            float4 xv = Xg4[gp * 64 + kq];
            float t0 = wv.x - xv.x, t1 = wv.y - xv.y;
            float t2 = wv.z - xv.z, t3 = wv.w - xv.w;
            float4 ov;
            ov.x = xv.x + t0; ov.y = xv.y + t1; ov.z = xv.z + t2; ov.w = xv.w + t3;
            long long e = gp * 64 + kq;
            if (e * 4 + 3 < out_cap) out4[e] = ov;
            dsum += t0 * t0 + t1 * t1 + t2 * t2 + t3 * t3;
        }
    }
    psum[tid] = dsum;
    __syncthreads();
    #pragma unroll
    for (int sft = 128; sft > 0; sft >>= 1) {
        if (tid < sft) psum[tid] += psum[tid + sft];
        __syncthreads();
    }
    if (tid == 0) atomicAdd(&g_devsum, (double)psum[0]);
}

__global__ void final_kernel(float* out, long long n, long long out_size) {
    double dev = 1.25 * g_devsum / (double)n;
    for (long long i = n + threadIdx.x; i < out_size; i += blockDim.x)
        out[i] = (float)dev;
}

// ================= launch ===========================================================
extern "C" void kernel_launch(void* const* d_in, const int* in_sizes, int n_in,
                              void* d_out, int out_size) {
    const float* X = (const float*)d_in[0];
    const float* W = (const float*)d_in[1];
    float* out = (float*)d_out;
    const int npix = in_sizes[0] / 256;
    const int S = in_sizes[1] / 256;

    cudaFuncSetAttribute(vq_kernel, cudaFuncAttributeMaxDynamicSharedMemorySize, SM_TOTAL);

    prep_kernel<<<S, 256>>>(W);
    vq_kernel<<<(npix + 127) / 128, 256, SM_TOTAL>>>(X, npix);
    candfix_kernel<<<296, 256>>>(X, W);
    gather_kernel<<<(npix + 127) / 128, 256>>>(X, W, out, npix, (long long)out_size);
    final_kernel<<<1, 256>>>(out, (long long)npix * 256, (long long)out_size);
}

// round 8
// speedup vs baseline: 3.5720x; 1.1792x over previous
#include <cuda_runtime.h>
#include <cuda_fp16.h>
#include <cstdint>

typedef unsigned long long u64;
typedef uint32_t u32;

__device__ double g_devsum;
__device__ int    g_flagcnt;
__device__ u32    g_wmaxb;          // zero-init; monotone atomicMax -> replay-deterministic
__device__ float  g_wnorm[1024];
__device__ int    g_code[65536];
__device__ int    g_flaglist[65536];
// [tile8][chunk4] regions of 16KB: SW128-swizzled [sym128][k64] fp16 (w scaled by 1024)
__device__ __align__(16) unsigned char g_wblob[32 * 16384];
// approximate scores: r = d_app - A, fp16, [pixel][sym] (2KB per pixel)
__device__ __align__(16) unsigned short g_dstore[65536 * 1024];

__device__ __forceinline__ u32 smem_to_u32(const void* p) {
    u32 a;
    asm("{ .reg .u64 t; cvta.to.shared.u64 t, %1; cvt.u32.u64 %0, t; }" : "=r"(a) : "l"(p));
    return a;
}
#define SW128(o) ((o) ^ (((o) >> 3) & 0x70))

#define LDSM4(r0, r1, r2, r3, addr) \
    asm volatile("ldmatrix.sync.aligned.m8n8.x4.shared.b16 {%0,%1,%2,%3}, [%4];" \
                 : "=r"(r0), "=r"(r1), "=r"(r2), "=r"(r3) : "r"(addr))

#define MMA16816(c0, c1, c2, c3, a0, a1, a2, a3, b0, b1) \
    asm volatile("mma.sync.aligned.m16n8k16.row.col.f32.f16.f16.f32 " \
                 "{%0,%1,%2,%3},{%4,%5,%6,%7},{%8,%9},{%0,%1,%2,%3};" \
                 : "+f"(c0), "+f"(c1), "+f"(c2), "+f"(c3) \
                 : "r"(a0), "r"(a1), "r"(a2), "r"(a3), "r"(b0), "r"(b1))

#define CP_ASYNC16(dst, src) \
    asm volatile("cp.async.cg.shared.global [%0], [%1], 16;" :: "r"(dst), "l"(src))
#define CP_COMMIT() asm volatile("cp.async.commit_group;")
#define CP_WAIT1()  asm volatile("cp.async.wait_group 1;")
#define CP_WAIT0()  asm volatile("cp.async.wait_group 0;")

// ================= prep: wnorm + wmax + fp16 W blob (scaled 1024, SW128) ============
__global__ void prep_kernel(const float* __restrict__ W) {
    int s = blockIdx.x, tid = threadIdx.x;
    __shared__ float red[8], redm[8];
    float v = W[s * 256 + tid];
    float acc = v * v;
    float am = fabsf(v);
    #pragma unroll
    for (int o = 16; o; o >>= 1) {
        acc += __shfl_xor_sync(0xffffffffu, acc, o);
        am = fmaxf(am, __shfl_xor_sync(0xffffffffu, am, o));
    }
    if ((tid & 31) == 0) { red[tid >> 5] = acc; redm[tid >> 5] = am; }
    __syncthreads();
    if (tid == 0) {
        float t = 0.f, m = 0.f;
        #pragma unroll
        for (int i = 0; i < 8; i++) { t += red[i]; m = fmaxf(m, redm[i]); }
        g_wnorm[s] = t;
        atomicMax(&g_wmaxb, __float_as_uint(m));
        if (s == 0) { g_devsum = 0.0; g_flagcnt = 0; }
    }
    int tile = s >> 7, sym = s & 127, c = tid >> 6, k = tid & 63;
    __half h = __float2half(v * 1024.0f);
    u32 off = SW128((u32)(sym * 128 + k * 2));
    *(__half*)(g_wblob + (size_t)(tile * 4 + c) * 16384 + off) = h;
}

// ================= vq: fp16 HMMA GEMM + margin argmin + d-store, 2 CTA/SM ===========
#define SM_A     0          // 128 rows x 512B, chunk^row swizzled = 65536
#define SM_BBUF  65536      // 2 x 16384, SW128 layout
#define SM_PART  65536      // phase-0 overlay: 128 x 65 floats = 33280
#define SM_RED   65536      // post-loop overlay: 128 x 16 x 2 u64 = 32768
#define SM_AROW  98816      // 128 floats
#define SM_TOTAL 99328

extern __shared__ char smem[];

__global__ void __launch_bounds__(256, 2)
vq_kernel(const float* __restrict__ X, int npix)
{
    const int tid = threadIdx.x, lane = tid & 31, wid = tid >> 5;
    const int warp_m = wid & 1, warp_n = wid >> 1;
    const int p0 = blockIdx.x * 128;
    const u32 sb = smem_to_u32(smem);

    // ---- phase 0: X -> fp16 A smem (swizzled) + x^2 quad partials ----
    float* part = (float*)(smem + SM_PART);
    const float4* Xg4 = (const float4*)X;
    #pragma unroll 4
    for (int i = 0; i < 32; i++) {
        int q = i * 256 + tid, row = q >> 6, kq = q & 63;
        float4 v = make_float4(0.f, 0.f, 0.f, 0.f);
        if (p0 + row < npix) v = Xg4[(size_t)(p0 + row) * 64 + kq];
        __half h0 = __float2half(v.x), h1 = __float2half(v.y);
        __half h2 = __float2half(v.z), h3 = __float2half(v.w);
        u32 hx = (u32)__half_as_ushort(h0) | ((u32)__half_as_ushort(h1) << 16);
        u32 hy = (u32)__half_as_ushort(h2) | ((u32)__half_as_ushort(h3) << 16);
        u32 aoff = (u32)(row * 512 + ((((kq >> 1) ^ (row & 7))) << 4) + (kq & 1) * 8);
        *(uint2*)(smem + SM_A + aoff) = make_uint2(hx, hy);
        part[row * 65 + kq] = ((v.x * v.x + v.y * v.y) + v.z * v.z) + v.w * v.w;
    }
    __syncthreads();
    float* arow = (float*)(smem + SM_AROW);
    if (tid < 128) {
        float a = 0.f;
        #pragma unroll
        for (int kq = 0; kq < 64; kq++) a += part[tid * 65 + kq];
        arow[tid] = a;
    }
    __syncthreads();
    float a_r[4][2];
    #pragma unroll
    for (int g = 0; g < 4; g++)
        #pragma unroll
        for (int h = 0; h < 2; h++)
            a_r[g][h] = arow[warp_m * 64 + g * 16 + (lane >> 2) + h * 8];
    __syncthreads();

    // ---- async B pipeline (blob is pre-swizzled -> identity copy) ----
    auto issue_copy = [&](int g, int buf) {
        #pragma unroll
        for (int j = 0; j < 4; j++) {
            int idx = j * 256 + tid;
            u32 dst = sb + SM_BBUF + (u32)(buf * 16384 + idx * 16);
            const char* src = (const char*)g_wblob + (size_t)g * 16384 + (size_t)idx * 16;
            CP_ASYNC16(dst, src);
        }
        CP_COMMIT();
    };
    issue_copy(0, 0);
    issue_copy(1, 1);

    float acc[4][4][4];
    #pragma unroll
    for (int g = 0; g < 4; g++)
        #pragma unroll
        for (int n = 0; n < 4; n++)
            #pragma unroll
            for (int j = 0; j < 4; j++) acc[g][n][j] = 0.f;
    u64 m1[4][2], m2[4][2];
    #pragma unroll
    for (int g = 0; g < 4; g++) { m1[g][0] = m1[g][1] = ~0ull; m2[g][0] = m2[g][1] = ~0ull; }

    // per-lane A row bases (4 gi values) and B sym bases (2 n2 values)
    u32 arb[4], arx[4];
    #pragma unroll
    for (int gi = 0; gi < 4; gi++) {
        int r = warp_m * 64 + gi * 16 + (lane & 15);
        arb[gi] = sb + SM_A + (u32)(r * 512);
        arx[gi] = (u32)(r & 7);
    }
    const u32 as16 = (u32)(lane >> 4);          // extra chunk bit from lane
    u32 brb[2], brx[2];
    #pragma unroll
    for (int n2 = 0; n2 < 2; n2++) {
        int sym = warp_n * 32 + n2 * 16 + (lane & 7) + (lane >> 4) * 8;
        brb[n2] = sb + SM_BBUF + (u32)(sym * 128);
        brx[n2] = (u32)(sym & 7);
    }
    const u32 bs0 = (u32)((lane >> 3) & 1);

    for (int g = 0; g < 32; g++) {
        const int tile = g >> 2, c = g & 3, buf = g & 1;
        if (g == 31) { CP_WAIT0(); } else { CP_WAIT1(); }
        __syncthreads();
        #pragma unroll
        for (int ks = 0; ks < 4; ks++) {
            u32 af[4][4], bfr[2][4];
            const u32 ch = (u32)(c * 8 + ks * 2) + as16;
            #pragma unroll
            for (int gi = 0; gi < 4; gi++)
                LDSM4(af[gi][0], af[gi][1], af[gi][2], af[gi][3],
                      arb[gi] + ((ch ^ arx[gi]) << 4));
            const u32 bseg = (u32)(ks * 2) + bs0;
            #pragma unroll
            for (int n2 = 0; n2 < 2; n2++)
                LDSM4(bfr[n2][0], bfr[n2][1], bfr[n2][2], bfr[n2][3],
                      brb[n2] + (u32)(buf * 16384) + ((bseg ^ brx[n2]) << 4));
            #pragma unroll
            for (int gi = 0; gi < 4; gi++)
                #pragma unroll
                for (int nf = 0; nf < 4; nf++)
                    MMA16816(acc[gi][nf][0], acc[gi][nf][1], acc[gi][nf][2], acc[gi][nf][3],
                             af[gi][0], af[gi][1], af[gi][2], af[gi][3],
                             bfr[nf >> 1][(nf & 1) * 2], bfr[nf >> 1][(nf & 1) * 2 + 1]);
        }
        if (c == 3) {
            // d = fl(fl(A+B) - 2*(acc/1024)) ; -2^-9 exact in fma.  Also store r = d - A.
            const int tbase = tile * 128 + warp_n * 32;
            #pragma unroll
            for (int nf = 0; nf < 4; nf++) {
                const int sym0 = tbase + nf * 8 + (lane & 3) * 2;
                const float w0 = g_wnorm[sym0];
                const float w1 = g_wnorm[sym0 + 1];
                #pragma unroll
                for (int gi = 0; gi < 4; gi++) {
                    #pragma unroll
                    for (int h = 0; h < 2; h++) {
                        const int row = warp_m * 64 + gi * 16 + (lane >> 2) + h * 8;
                        float d0 = __fmaf_rn(-0.001953125f, acc[gi][nf][h * 2],
                                             __fadd_rn(a_r[gi][h], w0));
                        float d1 = __fmaf_rn(-0.001953125f, acc[gi][nf][h * 2 + 1],
                                             __fadd_rn(a_r[gi][h], w1));
                        if (p0 + row < npix) {
                            __half2 rp = __floats2half2_rn(__fsub_rn(d0, a_r[gi][h]),
                                                           __fsub_rn(d1, a_r[gi][h]));
                            *(u32*)(g_dstore + (size_t)(p0 + row) * 1024 + sym0) =
                                *(u32*)&rp;
                        }
                        u64 k0 = ((u64)__float_as_uint(d0) << 32) | (u32)sym0;
                        u64 k1 = ((u64)__float_as_uint(d1) << 32) | (u32)(sym0 + 1);
                        if (k0 < m1[gi][h]) { m2[gi][h] = m1[gi][h]; m1[gi][h] = k0; }
                        else if (k0 < m2[gi][h]) m2[gi][h] = k0;
                        if (k1 < m1[gi][h]) { m2[gi][h] = m1[gi][h]; m1[gi][h] = k1; }
                        else if (k1 < m2[gi][h]) m2[gi][h] = k1;
                        acc[gi][nf][h * 2] = 0.f;
                        acc[gi][nf][h * 2 + 1] = 0.f;
                    }
                }
            }
        }
        __syncthreads();
        if (g + 2 < 32) issue_copy(g + 2, buf);
    }

    // ---- top-2 merge + per-pixel certified margin (sabs from resident fp16 A) ----
    u64* red2 = (u64*)(smem + SM_RED);
    const int slot = warp_n * 4 + (lane & 3);
    #pragma unroll
    for (int gi = 0; gi < 4; gi++)
        #pragma unroll
        for (int h = 0; h < 2; h++) {
            int row = warp_m * 64 + gi * 16 + (lane >> 2) + h * 8;
            red2[(row * 16 + slot) * 2]     = m1[gi][h];
            red2[(row * 16 + slot) * 2 + 1] = m2[gi][h];
        }
    __syncthreads();
    if (tid < 128) {
        u64 b1 = ~0ull, b2 = ~0ull;
        #pragma unroll
        for (int t = 0; t < 16; t++) {
            u64 x1 = red2[(tid * 16 + t) * 2];
            u64 x2 = red2[(tid * 16 + t) * 2 + 1];
            if (x1 < b1) { u64 c2 = (b1 < x2) ? b1 : x2; b1 = x1; b2 = (c2 < b2) ? c2 : b2; }
            else if (x1 < b2) b2 = x1;
        }
        // |x| sum from fp16 A tile (bound input only; constant inflated for fp16 quant)
        float sab = 0.f;
        const u32 rx7 = (u32)(tid & 7);
        #pragma unroll 8
        for (u32 ch = 0; ch < 32; ch++) {
            uint4 v = *(const uint4*)(smem + SM_A + tid * 512 + ((ch ^ rx7) << 4));
            const u32 wd[4] = {v.x, v.y, v.z, v.w};
            #pragma unroll
            for (int t = 0; t < 4; t++) {
                float2 f = __half22float2(*(const __half2*)&wd[t]);
                sab += fabsf(f.x) + fabsf(f.y);
            }
        }
        if (p0 + tid < npix) {
            g_code[p0 + tid] = (int)(u32)b1;
            float d1 = __uint_as_float((u32)(b1 >> 32));
            float d2 = __uint_as_float((u32)(b2 >> 32));
            float wmax = __uint_as_float(g_wmaxb);
            float marg = sab * wmax * 0.00398f + 1.0e-4f;
            if (!(d2 - d1 > marg)) {
                int fs = atomicAdd(&g_flagcnt, 1);
                g_flaglist[fs] = p0 + tid;
            }
        }
    }
}

// ================= candfix: exact rescore of CANDIDATES only ========================
__device__ __forceinline__ u64 chain_key(const float* xr, const float* __restrict__ W,
                                         int sym, float A) {
    const float4* wp = (const float4*)(W + (size_t)sym * 256);
    float acc = 0.f;
    #pragma unroll 8
    for (int k = 0; k < 64; k++) {
        float4 w4 = __ldg(&wp[k]);
        float4 x4 = *(const float4*)(xr + k * 4);
        acc = __fmaf_rn(x4.x, w4.x, acc);
        acc = __fmaf_rn(x4.y, w4.y, acc);
        acc = __fmaf_rn(x4.z, w4.z, acc);
        acc = __fmaf_rn(x4.w, w4.w, acc);
    }
    float d = __fmaf_rn(-2.f, acc, __fadd_rn(A, g_wnorm[sym]));
    return ((u64)__float_as_uint(d) << 32) | (u32)sym;
}

__global__ void __launch_bounds__(256, 1)
candfix_kernel(const float* __restrict__ X, const float* __restrict__ W)
{
    __shared__ float xrow[8][256];
    __shared__ float pp[8][64];
    __shared__ int   clist[8][34];
    __shared__ int   scnt[8];
    __shared__ float sA[8];
    const int lane = threadIdx.x & 31, w = threadIdx.x >> 5;
    const int wg = blockIdx.x * 8 + w, nw = gridDim.x * 8;
    const int cnt = g_flagcnt;
    const float wmax = __uint_as_float(g_wmaxb);

    for (int i = wg; i < cnt; i += nw) {
        const int pixel = g_flaglist[i];
        float sabs_l = 0.f;
        #pragma unroll
        for (int j = 0; j < 2; j++) {
            int kq = lane + j * 32;
            float4 v = ((const float4*)X)[(size_t)pixel * 64 + kq];
            *(float4*)&xrow[w][kq * 4] = v;
            pp[w][kq] = ((v.x * v.x + v.y * v.y) + v.z * v.z) + v.w * v.w;
            sabs_l += ((fabsf(v.x) + fabsf(v.y)) + fabsf(v.z)) + fabsf(v.w);
        }
        if (lane == 0) scnt[w] = 0;
        __syncwarp();
        if (lane == 0) {
            float a = 0.f;
            #pragma unroll
            for (int k = 0; k < 64; k++) a += pp[w][k];
            sA[w] = a;
        }
        #pragma unroll
        for (int o = 16; o; o >>= 1) sabs_l += __shfl_xor_sync(0xffffffffu, sabs_l, o);
        __syncwarp();
        const float A = sA[w];

        const uint4* rrow = (const uint4*)(g_dstore + (size_t)pixel * 1024);
        uint4 rv[4];
        float rmin = 3.4e38f;
        #pragma unroll
        for (int j = 0; j < 4; j++) {
            rv[j] = rrow[lane * 4 + j];
            const u32 wd[4] = {rv[j].x, rv[j].y, rv[j].z, rv[j].w};
            #pragma unroll
            for (int t = 0; t < 4; t++) {
                float2 f = __half22float2(*(const __half2*)&wd[t]);
                rmin = fminf(rmin, fminf(f.x, f.y));
            }
        }
        #pragma unroll
        for (int o = 16; o; o >>= 1)
            rmin = fminf(rmin, __shfl_xor_sync(0xffffffffu, rmin, o));
        const float thr = rmin + sabs_l * wmax * 0.004f + 6.5e-4f;

        #pragma unroll
        for (int j = 0; j < 4; j++) {
            const u32 wd[4] = {rv[j].x, rv[j].y, rv[j].z, rv[j].w};
            #pragma unroll
            for (int t = 0; t < 4; t++) {
                float2 f = __half22float2(*(const __half2*)&wd[t]);
                int sym = (lane * 16 + j * 4 + t) * 2;
                if (f.x <= thr) {
                    int pos = atomicAdd(&scnt[w], 1);
                    if (pos < 33) clist[w][pos] = sym;
                }
                if (f.y <= thr) {
                    int pos = atomicAdd(&scnt[w], 1);
                    if (pos < 33) clist[w][pos] = sym + 1;
                }
            }
        }
        __syncwarp();
        const int n = scnt[w];
        u64 key = ~0ull;
        if (n <= 32) {
            if (lane < n) key = chain_key(xrow[w], W, clist[w][lane], A);
        } else {
            for (int sym = lane; sym < 1024; sym += 32) {
                u64 k2 = chain_key(xrow[w], W, sym, A);
                if (k2 < key) key = k2;
            }
        }
        #pragma unroll
        for (int o = 16; o; o >>= 1) {
            u64 other = __shfl_xor_sync(0xffffffffu, key, o);
            if (other < key) key = other;
        }
        if (lane == 0) g_code[pixel] = (int)(u32)key;
        __syncwarp();
    }
}

// ================= gather + deviation ===============================================
__global__ void gather_kernel(const float* __restrict__ X, const float* __restrict__ W,
                              float* __restrict__ out, int npix, long long out_cap)
{
    __shared__ float psum[256];
    __shared__ int codes[128];
    const int tid = threadIdx.x;
    const int p0 = blockIdx.x * 128;
    if (tid < 128) codes[tid] = (p0 + tid < npix) ? g_code[p0 + tid] : 0;
    __syncthreads();
    const float4* Xg4 = (const float4*)X;
    const float4* Wg4 = (const float4*)W;
    float4* out4 = (float4*)out;
    float dsum = 0.f;
    #pragma unroll 4
    for (int i = 0; i < 32; i++) {
        int q = i * 256 + tid, row = q >> 6, kq = q & 63;
        long long gp = p0 + row;
        if (gp < npix) {
            int c = codes[row];
            float4 wv = Wg4[(size_t)c * 64 + kq];
            float4 xv = Xg4[gp * 64 + kq];
            float t0 = wv.x - xv.x, t1 = wv.y - xv.y;
            float t2 = wv.z - xv.z, t3 = wv.w - xv.w;
            float4 ov;
            ov.x = xv.x + t0; ov.y = xv.y + t1; ov.z = xv.z + t2; ov.w = xv.w + t3;
            long long e = gp * 64 + kq;
            if (e * 4 + 3 < out_cap) out4[e] = ov;
            dsum += t0 * t0 + t1 * t1 + t2 * t2 + t3 * t3;
        }
    }
    psum[tid] = dsum;
    __syncthreads();
    #pragma unroll
    for (int sft = 128; sft > 0; sft >>= 1) {
        if (tid < sft) psum[tid] += psum[tid + sft];
        __syncthreads();
    }
    if (tid == 0) atomicAdd(&g_devsum, (double)psum[0]);
}

__global__ void final_kernel(float* out, long long n, long long out_size) {
    double dev = 1.25 * g_devsum / (double)n;
    for (long long i = n + threadIdx.x; i < out_size; i += blockDim.x)
        out[i] = (float)dev;
}

// ================= launch ===========================================================
extern "C" void kernel_launch(void* const* d_in, const int* in_sizes, int n_in,
                              void* d_out, int out_size) {
    const float* X = (const float*)d_in[0];
    const float* W = (const float*)d_in[1];
    float* out = (float*)d_out;
    const int npix = in_sizes[0] / 256;
    const int S = in_sizes[1] / 256;

    cudaFuncSetAttribute(vq_kernel, cudaFuncAttributeMaxDynamicSharedMemorySize, SM_TOTAL);

    prep_kernel<<<S, 256>>>(W);
    vq_kernel<<<(npix + 127) / 128, 256, SM_TOTAL>>>(X, npix);
    candfix_kernel<<<296, 256>>>(X, W);
    gather_kernel<<<(npix + 127) / 128, 256>>>(X, W, out, npix, (long long)out_size);
    final_kernel<<<1, 256>>>(out, (long long)npix * 256, (long long)out_size);
}